// round 1
// baseline (speedup 1.0000x reference)
#include <cuda_runtime.h>
#include <cuda_bf16.h>
#include <math.h>

// Problem constants
#define BB 2
#define SS 2048
#define DIM 2048
#define HH 16
#define KVR 512
#define NOPE 128
#define ROPE 64
#define VDIM 128
#define QK 192
#define BS (BB*SS)           // 4096
#define SCALE_C 0.07216878364870322f   // 192^-0.5
#define NEG_BIG -1e30f

// ---------------- scratch (static device globals; no allocation) ----------------
__device__ float g_Q  [(size_t)BS * (HH*QK)];     // 4096 x 3072
__device__ float g_KV [(size_t)BS * (KVR+ROPE)];  // 4096 x 576
__device__ float g_CKV[(size_t)BS * KVR];         // 4096 x 512
__device__ float g_KPE[(size_t)BS * ROPE];        // 4096 x 64
__device__ float g_KN [(size_t)BS * (HH*NOPE)];   // 4096 x 2048
__device__ float g_V  [(size_t)BS * (HH*VDIM)];   // 4096 x 2048
__device__ float g_OH [(size_t)BS * (HH*VDIM)];   // 4096 x 2048

// ---------------- generic tiled GEMM: C[M,N] = A[M,K] @ B'[N,K]^T ----------------
// B row remap: actual_row(n) = gbase + (n/group)*gstride + (n%group)
__global__ __launch_bounds__(256)
void gemm_abT(const float* __restrict__ A, const float* __restrict__ B,
              float* __restrict__ C, int M, int N, int K,
              int group, int gstride, int gbase)
{
    __shared__ float As[16][68];
    __shared__ float Bs[16][68];
    const int tid  = threadIdx.x;
    const int row0 = blockIdx.y * 64;
    const int col0 = blockIdx.x * 64;
    const int tr = tid >> 4;          // 0..15
    const int tc = tid & 15;          // 0..15
    const int lr = tid >> 2;          // 0..63
    const int lk = (tid & 3) << 2;    // 0,4,8,12

    const float* Ap = A + (size_t)(row0 + lr) * K + lk;
    const int bn   = col0 + lr;
    const int brow = gbase + (bn / group) * gstride + (bn % group);
    const float* Bp = B + (size_t)brow * K + lk;

    float acc[4][4];
    #pragma unroll
    for (int i = 0; i < 4; i++)
        #pragma unroll
        for (int j = 0; j < 4; j++) acc[i][j] = 0.f;

    for (int k0 = 0; k0 < K; k0 += 16) {
        float4 av = *(const float4*)(Ap + k0);
        float4 bv = *(const float4*)(Bp + k0);
        As[lk+0][lr] = av.x; As[lk+1][lr] = av.y; As[lk+2][lr] = av.z; As[lk+3][lr] = av.w;
        Bs[lk+0][lr] = bv.x; Bs[lk+1][lr] = bv.y; Bs[lk+2][lr] = bv.z; Bs[lk+3][lr] = bv.w;
        __syncthreads();
        #pragma unroll
        for (int kk = 0; kk < 16; kk++) {
            float4 a = *(const float4*)&As[kk][tr << 2];
            float4 b = *(const float4*)&Bs[kk][tc << 2];
            acc[0][0] += a.x*b.x; acc[0][1] += a.x*b.y; acc[0][2] += a.x*b.z; acc[0][3] += a.x*b.w;
            acc[1][0] += a.y*b.x; acc[1][1] += a.y*b.y; acc[1][2] += a.y*b.z; acc[1][3] += a.y*b.w;
            acc[2][0] += a.z*b.x; acc[2][1] += a.z*b.y; acc[2][2] += a.z*b.z; acc[2][3] += a.z*b.w;
            acc[3][0] += a.w*b.x; acc[3][1] += a.w*b.y; acc[3][2] += a.w*b.z; acc[3][3] += a.w*b.w;
        }
        __syncthreads();
    }
    float* Cp = C + (size_t)(row0 + (tr << 2)) * N + col0 + (tc << 2);
    #pragma unroll
    for (int i = 0; i < 4; i++) {
        float4 v = make_float4(acc[i][0], acc[i][1], acc[i][2], acc[i][3]);
        *(float4*)(Cp + (size_t)i * N) = v;
    }
}

// ---------------- RoPE on q_pe part of Q (in place) ----------------
__global__ void rope_q_kernel(float* __restrict__ Q,
                              const float* __restrict__ COS,
                              const float* __restrict__ SIN)
{
    int idx = blockIdx.x * blockDim.x + threadIdx.x;
    if (idx >= BS * HH * 32) return;
    int i = idx & 31;
    int h = (idx >> 5) & 15;
    int m = idx >> 9;
    int s = m & (SS - 1);
    size_t base = (size_t)m * (HH*QK) + h * QK + NOPE + 2*i;
    float xe = Q[base], xo = Q[base + 1];
    float c  = COS[s*32 + i], sn = SIN[s*32 + i];
    Q[base]     = xe*c - xo*sn;
    Q[base + 1] = xe*sn + xo*c;
}

// ---------------- KV post: rmsnorm(c_kv) and rope(k_pe) ----------------
__global__ void kv_post_kernel(const float* __restrict__ KV,
                               const float* __restrict__ W,
                               const float* __restrict__ COS,
                               const float* __restrict__ SIN,
                               float* __restrict__ CKV,
                               float* __restrict__ KPE)
{
    __shared__ float red[4];
    __shared__ float rs_s;
    const int m = blockIdx.x;
    const int tid = threadIdx.x; // 128 threads
    const float* row = KV + (size_t)m * (KVR+ROPE);

    float ss = 0.f;
    for (int c = tid; c < KVR; c += 128) { float v = row[c]; ss += v * v; }
    #pragma unroll
    for (int o = 16; o; o >>= 1) ss += __shfl_xor_sync(0xffffffffu, ss, o);
    if ((tid & 31) == 0) red[tid >> 5] = ss;
    __syncthreads();
    if (tid == 0) {
        float t = red[0] + red[1] + red[2] + red[3];
        rs_s = rsqrtf(t / (float)KVR + 1e-6f);
    }
    __syncthreads();
    float rs = rs_s;
    for (int c = tid; c < KVR; c += 128)
        CKV[(size_t)m * KVR + c] = row[c] * rs * W[c];

    if (tid < 32) {
        int i = tid;
        int s = m & (SS - 1);
        float xe = row[KVR + 2*i], xo = row[KVR + 2*i + 1];
        float c  = COS[s*32 + i], sn = SIN[s*32 + i];
        KPE[(size_t)m * ROPE + 2*i]     = xe*c - xo*sn;
        KPE[(size_t)m * ROPE + 2*i + 1] = xe*sn + xo*c;
    }
}

// ---------------- flash attention: d=192 (128 nope + 64 rope), dv=128 ----------------
// grid: (S/64, H, B), 256 threads, dynamic smem
__global__ __launch_bounds__(256, 1)
void attn_kernel(const float* __restrict__ Q,    // [BS, 3072]
                 const float* __restrict__ KN,   // [BS, 2048]
                 const float* __restrict__ KPE,  // [BS, 64]
                 const float* __restrict__ V,    // [BS, 2048]
                 float* __restrict__ O)          // [BS, 2048]
{
    extern __shared__ float smem[];
    float* sQ = smem;                  // [192][68]
    float* sK = sQ + 192*68;           // [192][68]
    float* sV = sK + 192*68;           // [64][132]
    float* sP = sV + 64*132;           // [64][68]
    float* sM = sP + 64*68;            // [64]
    float* sL = sM + 64;               // [64]
    float* sAl = sL + 64;              // [64]

    const int tid = threadIdx.x;
    const int q0  = blockIdx.x * 64;
    const int h   = blockIdx.y;
    const int b   = blockIdx.z;
    const int bs0 = b * SS;

    // load Q tile (transposed: sQ[d][r])
    for (int i = tid; i < 64*192; i += 256) {
        int r = i / 192, d = i % 192;
        sQ[d*68 + r] = Q[(size_t)(bs0 + q0 + r) * (HH*QK) + h*QK + d];
    }
    if (tid < 64) { sM[tid] = NEG_BIG; sL[tid] = 0.f; }

    const int tr = tid >> 4;   // row group (scores: 4 rows; acc: 4 rows)
    const int tc = tid & 15;   // col group (scores: 4 cols; acc: 8 cols)

    float acc[4][8];
    #pragma unroll
    for (int i = 0; i < 4; i++)
        #pragma unroll
        for (int j = 0; j < 8; j++) acc[i][j] = 0.f;

    __syncthreads();

    const int ntiles = q0/64 + 1;
    for (int tt = 0; tt < ntiles; tt++) {
        const int t0 = tt * 64;
        // load K tile (sK[d][t]) and V tile (sV[t][c])
        for (int i = tid; i < 64*192; i += 256) {
            int t = i / 192, d = i % 192;
            float v;
            if (d < NOPE) v = KN [(size_t)(bs0 + t0 + t) * (HH*NOPE) + h*NOPE + d];
            else          v = KPE[(size_t)(bs0 + t0 + t) * ROPE + (d - NOPE)];
            sK[d*68 + t] = v;
        }
        for (int i = tid; i < 64*128; i += 256) {
            int t = i >> 7, c = i & 127;
            sV[t*132 + c] = V[(size_t)(bs0 + t0 + t) * (HH*VDIM) + h*VDIM + c];
        }
        __syncthreads();

        // scores: 4x4 per thread over [64 x 64]
        float s[4][4];
        #pragma unroll
        for (int i = 0; i < 4; i++)
            #pragma unroll
            for (int j = 0; j < 4; j++) s[i][j] = 0.f;
        #pragma unroll 4
        for (int kk = 0; kk < 192; kk++) {
            float4 a = *(const float4*)&sQ[kk*68 + (tr << 2)];
            float4 k = *(const float4*)&sK[kk*68 + (tc << 2)];
            s[0][0] += a.x*k.x; s[0][1] += a.x*k.y; s[0][2] += a.x*k.z; s[0][3] += a.x*k.w;
            s[1][0] += a.y*k.x; s[1][1] += a.y*k.y; s[1][2] += a.y*k.z; s[1][3] += a.y*k.w;
            s[2][0] += a.z*k.x; s[2][1] += a.z*k.y; s[2][2] += a.z*k.z; s[2][3] += a.z*k.w;
            s[3][0] += a.w*k.x; s[3][1] += a.w*k.y; s[3][2] += a.w*k.z; s[3][3] += a.w*k.w;
        }
        #pragma unroll
        for (int i = 0; i < 4; i++) {
            int gr = q0 + (tr << 2) + i;
            #pragma unroll
            for (int j = 0; j < 4; j++) {
                int gc = t0 + (tc << 2) + j;
                float val = s[i][j] * SCALE_C;
                if (gc > gr) val = NEG_BIG;
                sP[((tr << 2) + i)*68 + (tc << 2) + j] = val;
            }
        }
        __syncthreads();

        // online softmax: 4 threads per row, 16 cols each
        {
            int r   = tid >> 2;
            int seg = tid & 3;
            float* prow = &sP[r*68 + seg*16];
            float mx = NEG_BIG;
            #pragma unroll
            for (int j = 0; j < 16; j++) mx = fmaxf(mx, prow[j]);
            #pragma unroll
            for (int o = 1; o < 4; o <<= 1) mx = fmaxf(mx, __shfl_xor_sync(0xffffffffu, mx, o));
            float mold = sM[r];
            float mnew = fmaxf(mold, mx);
            float alpha = __expf(mold - mnew);
            float lsum = 0.f;
            #pragma unroll
            for (int j = 0; j < 16; j++) {
                float e = __expf(prow[j] - mnew);
                prow[j] = e;
                lsum += e;
            }
            #pragma unroll
            for (int o = 1; o < 4; o <<= 1) lsum += __shfl_xor_sync(0xffffffffu, lsum, o);
            if (seg == 0) { sM[r] = mnew; sL[r] = sL[r]*alpha + lsum; sAl[r] = alpha; }
        }
        __syncthreads();

        // rescale + PV: each thread 4 rows x 8 cols
        #pragma unroll
        for (int i = 0; i < 4; i++) {
            float al = sAl[(tr << 2) + i];
            #pragma unroll
            for (int j = 0; j < 8; j++) acc[i][j] *= al;
        }
        #pragma unroll 2
        for (int t = 0; t < 64; t++) {
            float p0 = sP[((tr << 2) + 0)*68 + t];
            float p1 = sP[((tr << 2) + 1)*68 + t];
            float p2 = sP[((tr << 2) + 2)*68 + t];
            float p3 = sP[((tr << 2) + 3)*68 + t];
            float4 v0 = *(const float4*)&sV[t*132 + (tc << 3)];
            float4 v1 = *(const float4*)&sV[t*132 + (tc << 3) + 4];
            acc[0][0] += p0*v0.x; acc[0][1] += p0*v0.y; acc[0][2] += p0*v0.z; acc[0][3] += p0*v0.w;
            acc[0][4] += p0*v1.x; acc[0][5] += p0*v1.y; acc[0][6] += p0*v1.z; acc[0][7] += p0*v1.w;
            acc[1][0] += p1*v0.x; acc[1][1] += p1*v0.y; acc[1][2] += p1*v0.z; acc[1][3] += p1*v0.w;
            acc[1][4] += p1*v1.x; acc[1][5] += p1*v1.y; acc[1][6] += p1*v1.z; acc[1][7] += p1*v1.w;
            acc[2][0] += p2*v0.x; acc[2][1] += p2*v0.y; acc[2][2] += p2*v0.z; acc[2][3] += p2*v0.w;
            acc[2][4] += p2*v1.x; acc[2][5] += p2*v1.y; acc[2][6] += p2*v1.z; acc[2][7] += p2*v1.w;
            acc[3][0] += p3*v0.x; acc[3][1] += p3*v0.y; acc[3][2] += p3*v0.z; acc[3][3] += p3*v0.w;
            acc[3][4] += p3*v1.x; acc[3][5] += p3*v1.y; acc[3][6] += p3*v1.z; acc[3][7] += p3*v1.w;
        }
        __syncthreads();
    }

    // epilogue: normalize by l, write
    #pragma unroll
    for (int i = 0; i < 4; i++) {
        int r = (tr << 2) + i;
        float inv = 1.f / sL[r];
        float* op = &O[(size_t)(bs0 + q0 + r) * (HH*VDIM) + h*VDIM + (tc << 3)];
        float4 o0 = make_float4(acc[i][0]*inv, acc[i][1]*inv, acc[i][2]*inv, acc[i][3]*inv);
        float4 o1 = make_float4(acc[i][4]*inv, acc[i][5]*inv, acc[i][6]*inv, acc[i][7]*inv);
        *(float4*)op       = o0;
        *(float4*)(op + 4) = o1;
    }
}

// ---------------- launch ----------------
extern "C" void kernel_launch(void* const* d_in, const int* in_sizes, int n_in,
                              void* d_out, int out_size)
{
    const float* x      = (const float*)d_in[0];
    const float* wq     = (const float*)d_in[1];
    const float* wkv_a  = (const float*)d_in[2];
    const float* kvw    = (const float*)d_in[3];
    const float* wkv_b  = (const float*)d_in[4];
    const float* wo     = (const float*)d_in[5];
    const float* cosp   = (const float*)d_in[6];
    const float* sinp   = (const float*)d_in[7];
    float* out = (float*)d_out;

    float *Q, *KV, *CKV, *KPE, *KN, *V, *OH;
    cudaGetSymbolAddress((void**)&Q,   g_Q);
    cudaGetSymbolAddress((void**)&KV,  g_KV);
    cudaGetSymbolAddress((void**)&CKV, g_CKV);
    cudaGetSymbolAddress((void**)&KPE, g_KPE);
    cudaGetSymbolAddress((void**)&KN,  g_KN);
    cudaGetSymbolAddress((void**)&V,   g_V);
    cudaGetSymbolAddress((void**)&OH,  g_OH);

    const int ASMEM = (192*68*2 + 64*132 + 64*68 + 3*64) * 4; // 156416 B
    cudaFuncSetAttribute(attn_kernel, cudaFuncAttributeMaxDynamicSharedMemorySize, ASMEM);

    dim3 blk(256);
    const int BIGGRP = 1 << 30;

    // 1. Q = X @ Wq^T                          [4096,3072]
    gemm_abT<<<dim3(48, 64), blk>>>(x, wq, Q, BS, HH*QK, DIM, BIGGRP, 0, 0);
    // 2. rope q_pe in place
    rope_q_kernel<<<(BS*HH*32 + 255)/256, 256>>>(Q, cosp, sinp);
    // 3. KV = X @ Wkv_a^T                      [4096,576]
    gemm_abT<<<dim3(9, 64), blk>>>(x, wkv_a, KV, BS, KVR+ROPE, DIM, BIGGRP, 0, 0);
    // 4. rmsnorm + rope(k_pe)
    kv_post_kernel<<<BS, 128>>>(KV, kvw, cosp, sinp, CKV, KPE);
    // 5. k_nope[:, h*128+d] = CKV @ wkv_b[h*256+d,:]^T
    gemm_abT<<<dim3(32, 64), blk>>>(CKV, wkv_b, KN, BS, HH*NOPE, KVR, 128, 256, 0);
    // 6. v[:, h*128+d]     = CKV @ wkv_b[h*256+128+d,:]^T
    gemm_abT<<<dim3(32, 64), blk>>>(CKV, wkv_b, V, BS, HH*VDIM, KVR, 128, 256, 128);
    // 7. attention
    attn_kernel<<<dim3(SS/64, HH, BB), 256, ASMEM>>>(Q, KN, KPE, V, OH);
    // 8. out = OH @ wo^T
    gemm_abT<<<dim3(32, 64), blk>>>(OH, wo, out, BS, DIM, HH*VDIM, BIGGRP, 0, 0);
}

// round 2
// speedup vs baseline: 1.4182x; 1.4182x over previous
#include <cuda_runtime.h>
#include <cuda_bf16.h>
#include <math.h>
#include <stdint.h>

// Problem constants
#define BB 2
#define SS 2048
#define DIM 2048
#define HH 16
#define KVR 512
#define NOPE 128
#define ROPE 64
#define VDIM 128
#define QK 192
#define BS (BB*SS)           // 4096
#define SCALE_C 0.07216878364870322f   // 192^-0.5
#define NEG_BIG -1e30f

// ---------------- scratch (static device globals; no allocation) ----------------
__device__ float g_Q  [(size_t)BS * (HH*QK)];     // 4096 x 3072
__device__ float g_KV [(size_t)BS * (KVR+ROPE)];  // 4096 x 576
__device__ float g_CKV[(size_t)BS * KVR];         // 4096 x 512
__device__ float g_KPE[(size_t)BS * ROPE];        // 4096 x 64
__device__ float g_KN [(size_t)BS * (HH*NOPE)];   // 4096 x 2048
__device__ float g_V  [(size_t)BS * (HH*VDIM)];   // 4096 x 2048
__device__ float g_OH [(size_t)BS * (HH*VDIM)];   // 4096 x 2048

// ---------------- tf32 helpers ----------------
__device__ __forceinline__ uint32_t f2tf32(float x) {
    uint32_t r;
    asm("cvt.rna.tf32.f32 %0, %1;" : "=r"(r) : "f"(x));
    return r;
}

__device__ __forceinline__ void mma_tf32(float& c0, float& c1, float& c2, float& c3,
                                         uint32_t a0, uint32_t a1, uint32_t a2, uint32_t a3,
                                         uint32_t b0, uint32_t b1)
{
    asm volatile(
        "mma.sync.aligned.m16n8k8.row.col.f32.tf32.tf32.f32 "
        "{%0,%1,%2,%3}, {%4,%5,%6,%7}, {%8,%9}, {%0,%1,%2,%3};\n"
        : "+f"(c0), "+f"(c1), "+f"(c2), "+f"(c3)
        : "r"(a0), "r"(a1), "r"(a2), "r"(a3), "r"(b0), "r"(b1));
}

// ---------------- tf32 tensor-core GEMM: C[M,N] = A[M,K] @ B'[N,K]^T ----------------
// B row remap: actual_row(n) = gbase + (n/group)*gstride + (n%group)
// CTA tile 128x128, 8 warps (2 m x 4 n), warp tile 64x32, k-chunk 16, double buffered.
#define GSTR 136   // smem row stride (floats): banks 8*tg+g -> conflict-free frags
__global__ __launch_bounds__(256)
void gemm_tf32(const float* __restrict__ A, const float* __restrict__ B,
               float* __restrict__ C, int M, int N, int K,
               int group, int gstride, int gbase)
{
    __shared__ uint32_t As[2][16][GSTR];
    __shared__ uint32_t Bs[2][16][GSTR];

    const int tid  = threadIdx.x;
    const int lane = tid & 31;
    const int warp = tid >> 5;
    const int row0 = blockIdx.y * 128;
    const int col0 = blockIdx.x * 128;

    const int warp_m = (warp & 1) * 64;   // 2 warps in m
    const int warp_n = (warp >> 1) * 32;  // 4 warps in n
    const int g  = lane >> 2;             // 0..7
    const int tg = lane & 3;              // 0..3

    // loader mapping: m/n = tid>>1 (0..127), kh = (tid&1)*8
    const int lm = tid >> 1;
    const int kh = (tid & 1) << 3;
    const float* Ap = A + (size_t)(row0 + lm) * K + kh;
    const int bn   = col0 + lm;
    const bool bok = (bn < N);
    int brow = 0;
    if (bok) brow = gbase + (bn / group) * gstride + (bn % group);
    const float* Bp = B + (size_t)brow * K + kh;

    float acc[4][4][4];   // [m-frag][n-frag][reg]
    #pragma unroll
    for (int i = 0; i < 4; i++)
        #pragma unroll
        for (int j = 0; j < 4; j++)
            #pragma unroll
            for (int r = 0; r < 4; r++) acc[i][j][r] = 0.f;

    const int nk = K >> 4;

    // prologue: tile 0
    {
        float4 a0 = *(const float4*)(Ap);
        float4 a1 = *(const float4*)(Ap + 4);
        float4 b0 = make_float4(0,0,0,0), b1 = make_float4(0,0,0,0);
        if (bok) { b0 = *(const float4*)(Bp); b1 = *(const float4*)(Bp + 4); }
        As[0][kh+0][lm]=f2tf32(a0.x); As[0][kh+1][lm]=f2tf32(a0.y);
        As[0][kh+2][lm]=f2tf32(a0.z); As[0][kh+3][lm]=f2tf32(a0.w);
        As[0][kh+4][lm]=f2tf32(a1.x); As[0][kh+5][lm]=f2tf32(a1.y);
        As[0][kh+6][lm]=f2tf32(a1.z); As[0][kh+7][lm]=f2tf32(a1.w);
        Bs[0][kh+0][lm]=f2tf32(b0.x); Bs[0][kh+1][lm]=f2tf32(b0.y);
        Bs[0][kh+2][lm]=f2tf32(b0.z); Bs[0][kh+3][lm]=f2tf32(b0.w);
        Bs[0][kh+4][lm]=f2tf32(b1.x); Bs[0][kh+5][lm]=f2tf32(b1.y);
        Bs[0][kh+6][lm]=f2tf32(b1.z); Bs[0][kh+7][lm]=f2tf32(b1.w);
    }
    __syncthreads();

    for (int kt = 0; kt < nk; kt++) {
        const int cur = kt & 1;
        float4 na0, na1, nb0, nb1;
        const bool have_next = (kt + 1 < nk);
        if (have_next) {
            const int ko = (kt + 1) << 4;
            na0 = *(const float4*)(Ap + ko);
            na1 = *(const float4*)(Ap + ko + 4);
            nb0 = make_float4(0,0,0,0); nb1 = make_float4(0,0,0,0);
            if (bok) { nb0 = *(const float4*)(Bp + ko); nb1 = *(const float4*)(Bp + ko + 4); }
        }

        // compute current buffer: two k8 sub-steps
        #pragma unroll
        for (int kk = 0; kk < 2; kk++) {
            const int k8 = kk << 3;
            uint32_t af[4][4], bf[4][2];
            #pragma unroll
            for (int im = 0; im < 4; im++) {
                int mb = warp_m + (im << 4);
                af[im][0] = As[cur][k8 + tg    ][mb + g];
                af[im][1] = As[cur][k8 + tg    ][mb + g + 8];
                af[im][2] = As[cur][k8 + tg + 4][mb + g];
                af[im][3] = As[cur][k8 + tg + 4][mb + g + 8];
            }
            #pragma unroll
            for (int in_ = 0; in_ < 4; in_++) {
                int nb = warp_n + (in_ << 3);
                bf[in_][0] = Bs[cur][k8 + tg    ][nb + g];
                bf[in_][1] = Bs[cur][k8 + tg + 4][nb + g];
            }
            #pragma unroll
            for (int im = 0; im < 4; im++)
                #pragma unroll
                for (int in_ = 0; in_ < 4; in_++)
                    mma_tf32(acc[im][in_][0], acc[im][in_][1], acc[im][in_][2], acc[im][in_][3],
                             af[im][0], af[im][1], af[im][2], af[im][3],
                             bf[in_][0], bf[in_][1]);
        }

        if (have_next) {
            const int nx = cur ^ 1;
            As[nx][kh+0][lm]=f2tf32(na0.x); As[nx][kh+1][lm]=f2tf32(na0.y);
            As[nx][kh+2][lm]=f2tf32(na0.z); As[nx][kh+3][lm]=f2tf32(na0.w);
            As[nx][kh+4][lm]=f2tf32(na1.x); As[nx][kh+5][lm]=f2tf32(na1.y);
            As[nx][kh+6][lm]=f2tf32(na1.z); As[nx][kh+7][lm]=f2tf32(na1.w);
            Bs[nx][kh+0][lm]=f2tf32(nb0.x); Bs[nx][kh+1][lm]=f2tf32(nb0.y);
            Bs[nx][kh+2][lm]=f2tf32(nb0.z); Bs[nx][kh+3][lm]=f2tf32(nb0.w);
            Bs[nx][kh+4][lm]=f2tf32(nb1.x); Bs[nx][kh+5][lm]=f2tf32(nb1.y);
            Bs[nx][kh+6][lm]=f2tf32(nb1.z); Bs[nx][kh+7][lm]=f2tf32(nb1.w);
        }
        __syncthreads();
    }

    // epilogue: each fragment -> 2x float2 stores
    #pragma unroll
    for (int im = 0; im < 4; im++) {
        #pragma unroll
        for (int in_ = 0; in_ < 4; in_++) {
            int row = row0 + warp_m + (im << 4) + g;
            int col = col0 + warp_n + (in_ << 3) + tg * 2;
            if (col < N) {
                *(float2*)(C + (size_t)row * N + col) =
                    make_float2(acc[im][in_][0], acc[im][in_][1]);
                *(float2*)(C + (size_t)(row + 8) * N + col) =
                    make_float2(acc[im][in_][2], acc[im][in_][3]);
            }
        }
    }
}

// ---------------- RoPE on q_pe part of Q (in place) ----------------
__global__ void rope_q_kernel(float* __restrict__ Q,
                              const float* __restrict__ COS,
                              const float* __restrict__ SIN)
{
    int idx = blockIdx.x * blockDim.x + threadIdx.x;
    if (idx >= BS * HH * 32) return;
    int i = idx & 31;
    int h = (idx >> 5) & 15;
    int m = idx >> 9;
    int s = m & (SS - 1);
    size_t base = (size_t)m * (HH*QK) + h * QK + NOPE + 2*i;
    float xe = Q[base], xo = Q[base + 1];
    float c  = COS[s*32 + i], sn = SIN[s*32 + i];
    Q[base]     = xe*c - xo*sn;
    Q[base + 1] = xe*sn + xo*c;
}

// ---------------- KV post: rmsnorm(c_kv) and rope(k_pe) ----------------
__global__ void kv_post_kernel(const float* __restrict__ KV,
                               const float* __restrict__ W,
                               const float* __restrict__ COS,
                               const float* __restrict__ SIN,
                               float* __restrict__ CKV,
                               float* __restrict__ KPE)
{
    __shared__ float red[4];
    __shared__ float rs_s;
    const int m = blockIdx.x;
    const int tid = threadIdx.x; // 128 threads
    const float* row = KV + (size_t)m * (KVR+ROPE);

    float ss = 0.f;
    for (int c = tid; c < KVR; c += 128) { float v = row[c]; ss += v * v; }
    #pragma unroll
    for (int o = 16; o; o >>= 1) ss += __shfl_xor_sync(0xffffffffu, ss, o);
    if ((tid & 31) == 0) red[tid >> 5] = ss;
    __syncthreads();
    if (tid == 0) {
        float t = red[0] + red[1] + red[2] + red[3];
        rs_s = rsqrtf(t / (float)KVR + 1e-6f);
    }
    __syncthreads();
    float rs = rs_s;
    for (int c = tid; c < KVR; c += 128)
        CKV[(size_t)m * KVR + c] = row[c] * rs * W[c];

    if (tid < 32) {
        int i = tid;
        int s = m & (SS - 1);
        float xe = row[KVR + 2*i], xo = row[KVR + 2*i + 1];
        float c  = COS[s*32 + i], sn = SIN[s*32 + i];
        KPE[(size_t)m * ROPE + 2*i]     = xe*c - xo*sn;
        KPE[(size_t)m * ROPE + 2*i + 1] = xe*sn + xo*c;
    }
}

// ---------------- flash attention: d=192 (128 nope + 64 rope), dv=128 ----------------
// grid: (S/64, H, B), 256 threads, dynamic smem
__global__ __launch_bounds__(256, 1)
void attn_kernel(const float* __restrict__ Q,    // [BS, 3072]
                 const float* __restrict__ KN,   // [BS, 2048]
                 const float* __restrict__ KPE,  // [BS, 64]
                 const float* __restrict__ V,    // [BS, 2048]
                 float* __restrict__ O)          // [BS, 2048]
{
    extern __shared__ float smem[];
    float* sQ = smem;                  // [192][68]
    float* sK = sQ + 192*68;           // [192][68]
    float* sV = sK + 192*68;           // [64][132]
    float* sP = sV + 64*132;           // [64][68]
    float* sM = sP + 64*68;            // [64]
    float* sL = sM + 64;               // [64]
    float* sAl = sL + 64;              // [64]

    const int tid = threadIdx.x;
    const int q0  = blockIdx.x * 64;
    const int h   = blockIdx.y;
    const int b   = blockIdx.z;
    const int bs0 = b * SS;

    // load Q tile (transposed: sQ[d][r])
    for (int i = tid; i < 64*192; i += 256) {
        int r = i / 192, d = i % 192;
        sQ[d*68 + r] = Q[(size_t)(bs0 + q0 + r) * (HH*QK) + h*QK + d];
    }
    if (tid < 64) { sM[tid] = NEG_BIG; sL[tid] = 0.f; }

    const int tr = tid >> 4;   // row group (scores: 4 rows; acc: 4 rows)
    const int tc = tid & 15;   // col group (scores: 4 cols; acc: 8 cols)

    float acc[4][8];
    #pragma unroll
    for (int i = 0; i < 4; i++)
        #pragma unroll
        for (int j = 0; j < 8; j++) acc[i][j] = 0.f;

    __syncthreads();

    const int ntiles = q0/64 + 1;
    for (int tt = 0; tt < ntiles; tt++) {
        const int t0 = tt * 64;
        // load K tile (sK[d][t]) and V tile (sV[t][c])
        for (int i = tid; i < 64*192; i += 256) {
            int t = i / 192, d = i % 192;
            float v;
            if (d < NOPE) v = KN [(size_t)(bs0 + t0 + t) * (HH*NOPE) + h*NOPE + d];
            else          v = KPE[(size_t)(bs0 + t0 + t) * ROPE + (d - NOPE)];
            sK[d*68 + t] = v;
        }
        for (int i = tid; i < 64*128; i += 256) {
            int t = i >> 7, c = i & 127;
            sV[t*132 + c] = V[(size_t)(bs0 + t0 + t) * (HH*VDIM) + h*VDIM + c];
        }
        __syncthreads();

        // scores: 4x4 per thread over [64 x 64]
        float s[4][4];
        #pragma unroll
        for (int i = 0; i < 4; i++)
            #pragma unroll
            for (int j = 0; j < 4; j++) s[i][j] = 0.f;
        #pragma unroll 4
        for (int kk = 0; kk < 192; kk++) {
            float4 a = *(const float4*)&sQ[kk*68 + (tr << 2)];
            float4 k = *(const float4*)&sK[kk*68 + (tc << 2)];
            s[0][0] += a.x*k.x; s[0][1] += a.x*k.y; s[0][2] += a.x*k.z; s[0][3] += a.x*k.w;
            s[1][0] += a.y*k.x; s[1][1] += a.y*k.y; s[1][2] += a.y*k.z; s[1][3] += a.y*k.w;
            s[2][0] += a.z*k.x; s[2][1] += a.z*k.y; s[2][2] += a.z*k.z; s[2][3] += a.z*k.w;
            s[3][0] += a.w*k.x; s[3][1] += a.w*k.y; s[3][2] += a.w*k.z; s[3][3] += a.w*k.w;
        }
        #pragma unroll
        for (int i = 0; i < 4; i++) {
            int gr = q0 + (tr << 2) + i;
            #pragma unroll
            for (int j = 0; j < 4; j++) {
                int gc = t0 + (tc << 2) + j;
                float val = s[i][j] * SCALE_C;
                if (gc > gr) val = NEG_BIG;
                sP[((tr << 2) + i)*68 + (tc << 2) + j] = val;
            }
        }
        __syncthreads();

        // online softmax: 4 threads per row, 16 cols each
        {
            int r   = tid >> 2;
            int seg = tid & 3;
            float* prow = &sP[r*68 + seg*16];
            float mx = NEG_BIG;
            #pragma unroll
            for (int j = 0; j < 16; j++) mx = fmaxf(mx, prow[j]);
            #pragma unroll
            for (int o = 1; o < 4; o <<= 1) mx = fmaxf(mx, __shfl_xor_sync(0xffffffffu, mx, o));
            float mold = sM[r];
            float mnew = fmaxf(mold, mx);
            float alpha = __expf(mold - mnew);
            float lsum = 0.f;
            #pragma unroll
            for (int j = 0; j < 16; j++) {
                float e = __expf(prow[j] - mnew);
                prow[j] = e;
                lsum += e;
            }
            #pragma unroll
            for (int o = 1; o < 4; o <<= 1) lsum += __shfl_xor_sync(0xffffffffu, lsum, o);
            if (seg == 0) { sM[r] = mnew; sL[r] = sL[r]*alpha + lsum; sAl[r] = alpha; }
        }
        __syncthreads();

        // rescale + PV: each thread 4 rows x 8 cols
        #pragma unroll
        for (int i = 0; i < 4; i++) {
            float al = sAl[(tr << 2) + i];
            #pragma unroll
            for (int j = 0; j < 8; j++) acc[i][j] *= al;
        }
        #pragma unroll 2
        for (int t = 0; t < 64; t++) {
            float p0 = sP[((tr << 2) + 0)*68 + t];
            float p1 = sP[((tr << 2) + 1)*68 + t];
            float p2 = sP[((tr << 2) + 2)*68 + t];
            float p3 = sP[((tr << 2) + 3)*68 + t];
            float4 v0 = *(const float4*)&sV[t*132 + (tc << 3)];
            float4 v1 = *(const float4*)&sV[t*132 + (tc << 3) + 4];
            acc[0][0] += p0*v0.x; acc[0][1] += p0*v0.y; acc[0][2] += p0*v0.z; acc[0][3] += p0*v0.w;
            acc[0][4] += p0*v1.x; acc[0][5] += p0*v1.y; acc[0][6] += p0*v1.z; acc[0][7] += p0*v1.w;
            acc[1][0] += p1*v0.x; acc[1][1] += p1*v0.y; acc[1][2] += p1*v0.z; acc[1][3] += p1*v0.w;
            acc[1][4] += p1*v1.x; acc[1][5] += p1*v1.y; acc[1][6] += p1*v1.z; acc[1][7] += p1*v1.w;
            acc[2][0] += p2*v0.x; acc[2][1] += p2*v0.y; acc[2][2] += p2*v0.z; acc[2][3] += p2*v0.w;
            acc[2][4] += p2*v1.x; acc[2][5] += p2*v1.y; acc[2][6] += p2*v1.z; acc[2][7] += p2*v1.w;
            acc[3][0] += p3*v0.x; acc[3][1] += p3*v0.y; acc[3][2] += p3*v0.z; acc[3][3] += p3*v0.w;
            acc[3][4] += p3*v1.x; acc[3][5] += p3*v1.y; acc[3][6] += p3*v1.z; acc[3][7] += p3*v1.w;
        }
        __syncthreads();
    }

    // epilogue: normalize by l, write
    #pragma unroll
    for (int i = 0; i < 4; i++) {
        int r = (tr << 2) + i;
        float inv = 1.f / sL[r];
        float* op = &O[(size_t)(bs0 + q0 + r) * (HH*VDIM) + h*VDIM + (tc << 3)];
        float4 o0 = make_float4(acc[i][0]*inv, acc[i][1]*inv, acc[i][2]*inv, acc[i][3]*inv);
        float4 o1 = make_float4(acc[i][4]*inv, acc[i][5]*inv, acc[i][6]*inv, acc[i][7]*inv);
        *(float4*)op       = o0;
        *(float4*)(op + 4) = o1;
    }
}

// ---------------- launch ----------------
extern "C" void kernel_launch(void* const* d_in, const int* in_sizes, int n_in,
                              void* d_out, int out_size)
{
    const float* x      = (const float*)d_in[0];
    const float* wq     = (const float*)d_in[1];
    const float* wkv_a  = (const float*)d_in[2];
    const float* kvw    = (const float*)d_in[3];
    const float* wkv_b  = (const float*)d_in[4];
    const float* wo     = (const float*)d_in[5];
    const float* cosp   = (const float*)d_in[6];
    const float* sinp   = (const float*)d_in[7];
    float* out = (float*)d_out;

    float *Q, *KV, *CKV, *KPE, *KN, *V, *OH;
    cudaGetSymbolAddress((void**)&Q,   g_Q);
    cudaGetSymbolAddress((void**)&KV,  g_KV);
    cudaGetSymbolAddress((void**)&CKV, g_CKV);
    cudaGetSymbolAddress((void**)&KPE, g_KPE);
    cudaGetSymbolAddress((void**)&KN,  g_KN);
    cudaGetSymbolAddress((void**)&V,   g_V);
    cudaGetSymbolAddress((void**)&OH,  g_OH);

    const int ASMEM = (192*68*2 + 64*132 + 64*68 + 3*64) * 4; // 156416 B
    cudaFuncSetAttribute(attn_kernel, cudaFuncAttributeMaxDynamicSharedMemorySize, ASMEM);

    dim3 blk(256);
    const int BIGGRP = 1 << 30;

    // 1. Q = X @ Wq^T                          [4096,3072]
    gemm_tf32<<<dim3(24, 32), blk>>>(x, wq, Q, BS, HH*QK, DIM, BIGGRP, 0, 0);
    // 2. rope q_pe in place
    rope_q_kernel<<<(BS*HH*32 + 255)/256, 256>>>(Q, cosp, sinp);
    // 3. KV = X @ Wkv_a^T                      [4096,576]
    gemm_tf32<<<dim3(5, 32), blk>>>(x, wkv_a, KV, BS, KVR+ROPE, DIM, BIGGRP, 0, 0);
    // 4. rmsnorm + rope(k_pe)
    kv_post_kernel<<<BS, 128>>>(KV, kvw, cosp, sinp, CKV, KPE);
    // 5. k_nope[:, h*128+d] = CKV @ wkv_b[h*256+d,:]^T
    gemm_tf32<<<dim3(16, 32), blk>>>(CKV, wkv_b, KN, BS, HH*NOPE, KVR, 128, 256, 0);
    // 6. v[:, h*128+d]     = CKV @ wkv_b[h*256+128+d,:]^T
    gemm_tf32<<<dim3(16, 32), blk>>>(CKV, wkv_b, V, BS, HH*VDIM, KVR, 128, 256, 128);
    // 7. attention
    attn_kernel<<<dim3(SS/64, HH, BB), 256, ASMEM>>>(Q, KN, KPE, V, OH);
    // 8. out = OH @ wo^T
    gemm_tf32<<<dim3(16, 32), blk>>>(OH, wo, out, BS, DIM, HH*VDIM, BIGGRP, 0, 0);
}

// round 3
// speedup vs baseline: 3.1339x; 2.2098x over previous
#include <cuda_runtime.h>
#include <cuda_bf16.h>
#include <math.h>
#include <stdint.h>

// Problem constants
#define BB 2
#define SS 2048
#define DIM 2048
#define HH 16
#define KVR 512
#define NOPE 128
#define ROPE 64
#define VDIM 128
#define QK 192
#define BS (BB*SS)           // 4096
#define SCALE_C 0.07216878364870322f   // 192^-0.5
#define NEG_BIG -1e30f

// ---------------- scratch (static device globals; no allocation) ----------------
__device__ float g_Q  [(size_t)BS * (HH*QK)];     // 4096 x 3072
__device__ float g_KV [(size_t)BS * (KVR+ROPE)];  // 4096 x 576
__device__ float g_CKV[(size_t)BS * KVR];         // 4096 x 512
__device__ float g_KPE[(size_t)BS * ROPE];        // 4096 x 64
__device__ float g_KN [(size_t)BS * (HH*NOPE)];   // 4096 x 2048
__device__ float g_V  [(size_t)BS * (HH*VDIM)];   // 4096 x 2048
__device__ float g_OH [(size_t)BS * (HH*VDIM)];   // 4096 x 2048
// pre-rounded (tf32) copies
__device__ float g_Xr [(size_t)BS * DIM];         // 4096 x 2048
__device__ float g_WQr[(size_t)(HH*QK) * DIM];    // 3072 x 2048
__device__ float g_WAr[(size_t)(KVR+ROPE) * DIM]; // 576 x 2048
__device__ float g_WBr[(size_t)(HH*(NOPE+VDIM)) * KVR]; // 4096 x 512
__device__ float g_WOr[(size_t)DIM * (HH*VDIM)];  // 2048 x 2048

// ---------------- helpers ----------------
__device__ __forceinline__ uint32_t f2tf32(float x) {
    uint32_t r;
    asm("cvt.rna.tf32.f32 %0, %1;" : "=r"(r) : "f"(x));
    return r;
}
__device__ __forceinline__ float tfr(float x) { return __uint_as_float(f2tf32(x)); }

__device__ __forceinline__ void mma_tf32(float& c0, float& c1, float& c2, float& c3,
                                         uint32_t a0, uint32_t a1, uint32_t a2, uint32_t a3,
                                         uint32_t b0, uint32_t b1)
{
    asm volatile(
        "mma.sync.aligned.m16n8k8.row.col.f32.tf32.tf32.f32 "
        "{%0,%1,%2,%3}, {%4,%5,%6,%7}, {%8,%9}, {%0,%1,%2,%3};\n"
        : "+f"(c0), "+f"(c1), "+f"(c2), "+f"(c3)
        : "r"(a0), "r"(a1), "r"(a2), "r"(a3), "r"(b0), "r"(b1));
}

__device__ __forceinline__ void cp_async16(uint32_t saddr, const void* gptr, int src_bytes) {
    asm volatile("cp.async.cg.shared.global [%0], [%1], 16, %2;\n"
                 :: "r"(saddr), "l"(gptr), "r"(src_bytes));
}
__device__ __forceinline__ void cp_commit() { asm volatile("cp.async.commit_group;\n"); }
template<int N> __device__ __forceinline__ void cp_wait() {
    asm volatile("cp.async.wait_group %0;\n" :: "n"(N));
}

// ---------------- tf32 rounding pass ----------------
__global__ void round_tf32_kernel(const float4* __restrict__ src, float4* __restrict__ dst, int n4)
{
    int i = blockIdx.x * blockDim.x + threadIdx.x;
    if (i >= n4) return;
    float4 v = src[i];
    v.x = tfr(v.x); v.y = tfr(v.y); v.z = tfr(v.z); v.w = tfr(v.w);
    dst[i] = v;
}

// ---------------- tf32 tensor-core GEMM: C[M,N] = A[M,K] @ B'[N,K]^T ----------------
// Inputs must be pre-rounded to tf32. cp.async 3-stage pipeline, smem [m][k] stride 20.
// B row remap: actual_row(n) = gbase + (n/group)*gstride + (n%group)
#define NST 3
__global__ __launch_bounds__(256)
void gemm_tf32(const float* __restrict__ A, const float* __restrict__ B,
               float* __restrict__ C, int M, int N, int K,
               int group, int gstride, int gbase)
{
    __shared__ uint32_t As[NST][128][20];
    __shared__ uint32_t Bs[NST][128][20];

    const int tid  = threadIdx.x;
    const int lane = tid & 31;
    const int warp = tid >> 5;
    const int row0 = blockIdx.y * 128;
    const int col0 = blockIdx.x * 128;

    const int warp_m = (warp & 1) * 64;
    const int warp_n = (warp >> 1) * 32;
    const int g  = lane >> 2;
    const int tg = lane & 3;

    // loader: 2 quads per operand per thread per stage
    int r0q = (tid) >> 2,        kq0 = (tid & 3) << 2;
    int r1q = (tid + 256) >> 2,  kq1 = ((tid + 256) & 3) << 2;

    const float* A0 = A + (size_t)(row0 + r0q) * K + kq0;
    const float* A1 = A + (size_t)(row0 + r1q) * K + kq1;

    int bn0 = col0 + r0q, bn1 = col0 + r1q;
    int bok0 = (bn0 < N) ? 16 : 0;
    int bok1 = (bn1 < N) ? 16 : 0;
    int br0 = bok0 ? (gbase + (bn0 / group) * gstride + (bn0 % group)) : 0;
    int br1 = bok1 ? (gbase + (bn1 / group) * gstride + (bn1 % group)) : 0;
    const float* B0 = B + (size_t)br0 * K + kq0;
    const float* B1 = B + (size_t)br1 * K + kq1;

    uint32_t sa0[NST], sa1[NST], sb0[NST], sb1[NST];
    #pragma unroll
    for (int s = 0; s < NST; s++) {
        sa0[s] = (uint32_t)__cvta_generic_to_shared(&As[s][r0q][kq0]);
        sa1[s] = (uint32_t)__cvta_generic_to_shared(&As[s][r1q][kq1]);
        sb0[s] = (uint32_t)__cvta_generic_to_shared(&Bs[s][r0q][kq0]);
        sb1[s] = (uint32_t)__cvta_generic_to_shared(&Bs[s][r1q][kq1]);
    }

    float acc[4][4][4];
    #pragma unroll
    for (int i = 0; i < 4; i++)
        #pragma unroll
        for (int j = 0; j < 4; j++)
            #pragma unroll
            for (int r = 0; r < 4; r++) acc[i][j][r] = 0.f;

    const int nk = K >> 4;

    // preload stages 0..NST-2
    #pragma unroll
    for (int s = 0; s < NST - 1; s++) {
        int ko = s << 4;
        cp_async16(sa0[s], A0 + ko, 16);
        cp_async16(sa1[s], A1 + ko, 16);
        cp_async16(sb0[s], B0 + ko, bok0);
        cp_async16(sb1[s], B1 + ko, bok1);
        cp_commit();
    }

    for (int kt = 0; kt < nk; kt++) {
        const int st = kt % NST;
        cp_wait<NST - 2>();
        __syncthreads();

        #pragma unroll
        for (int kk = 0; kk < 16; kk += 8) {
            uint32_t af[4][4], bf[4][2];
            #pragma unroll
            for (int im = 0; im < 4; im++) {
                int mb = warp_m + (im << 4);
                af[im][0] = As[st][mb + g    ][kk + tg];
                af[im][1] = As[st][mb + g + 8][kk + tg];
                af[im][2] = As[st][mb + g    ][kk + tg + 4];
                af[im][3] = As[st][mb + g + 8][kk + tg + 4];
            }
            #pragma unroll
            for (int in_ = 0; in_ < 4; in_++) {
                int nb = warp_n + (in_ << 3);
                bf[in_][0] = Bs[st][nb + g][kk + tg];
                bf[in_][1] = Bs[st][nb + g][kk + tg + 4];
            }
            #pragma unroll
            for (int im = 0; im < 4; im++)
                #pragma unroll
                for (int in_ = 0; in_ < 4; in_++)
                    mma_tf32(acc[im][in_][0], acc[im][in_][1], acc[im][in_][2], acc[im][in_][3],
                             af[im][0], af[im][1], af[im][2], af[im][3],
                             bf[in_][0], bf[in_][1]);
        }
        __syncthreads();

        int knext = kt + NST - 1;
        if (knext < nk) {
            int sn = knext % NST;
            int ko = knext << 4;
            cp_async16(sa0[sn], A0 + ko, 16);
            cp_async16(sa1[sn], A1 + ko, 16);
            cp_async16(sb0[sn], B0 + ko, bok0);
            cp_async16(sb1[sn], B1 + ko, bok1);
        }
        cp_commit();
    }

    #pragma unroll
    for (int im = 0; im < 4; im++) {
        #pragma unroll
        for (int in_ = 0; in_ < 4; in_++) {
            int row = row0 + warp_m + (im << 4) + g;
            int col = col0 + warp_n + (in_ << 3) + tg * 2;
            if (col < N) {
                *(float2*)(C + (size_t)row * N + col) =
                    make_float2(acc[im][in_][0], acc[im][in_][1]);
                *(float2*)(C + (size_t)(row + 8) * N + col) =
                    make_float2(acc[im][in_][2], acc[im][in_][3]);
            }
        }
    }
}

// ---------------- RoPE on q_pe part of Q (in place) ----------------
__global__ void rope_q_kernel(float* __restrict__ Q,
                              const float* __restrict__ COS,
                              const float* __restrict__ SIN)
{
    int idx = blockIdx.x * blockDim.x + threadIdx.x;
    if (idx >= BS * HH * 32) return;
    int i = idx & 31;
    int h = (idx >> 5) & 15;
    int m = idx >> 9;
    int s = m & (SS - 1);
    size_t base = (size_t)m * (HH*QK) + h * QK + NOPE + 2*i;
    float xe = Q[base], xo = Q[base + 1];
    float c  = COS[s*32 + i], sn = SIN[s*32 + i];
    Q[base]     = xe*c - xo*sn;
    Q[base + 1] = xe*sn + xo*c;
}

// ---------------- KV post: rmsnorm(c_kv) (tf32-rounded out) and rope(k_pe) ----------------
__global__ void kv_post_kernel(const float* __restrict__ KV,
                               const float* __restrict__ W,
                               const float* __restrict__ COS,
                               const float* __restrict__ SIN,
                               float* __restrict__ CKV,
                               float* __restrict__ KPE)
{
    __shared__ float red[4];
    __shared__ float rs_s;
    const int m = blockIdx.x;
    const int tid = threadIdx.x; // 128 threads
    const float* row = KV + (size_t)m * (KVR+ROPE);

    float ss = 0.f;
    for (int c = tid; c < KVR; c += 128) { float v = row[c]; ss += v * v; }
    #pragma unroll
    for (int o = 16; o; o >>= 1) ss += __shfl_xor_sync(0xffffffffu, ss, o);
    if ((tid & 31) == 0) red[tid >> 5] = ss;
    __syncthreads();
    if (tid == 0) {
        float t = red[0] + red[1] + red[2] + red[3];
        rs_s = rsqrtf(t / (float)KVR + 1e-6f);
    }
    __syncthreads();
    float rs = rs_s;
    for (int c = tid; c < KVR; c += 128)
        CKV[(size_t)m * KVR + c] = tfr(row[c] * rs * W[c]);

    if (tid < 32) {
        int i = tid;
        int s = m & (SS - 1);
        float xe = row[KVR + 2*i], xo = row[KVR + 2*i + 1];
        float c  = COS[s*32 + i], sn = SIN[s*32 + i];
        KPE[(size_t)m * ROPE + 2*i]     = xe*c - xo*sn;
        KPE[(size_t)m * ROPE + 2*i + 1] = xe*sn + xo*c;
    }
}

// ---------------- flash attention with tf32 mma ----------------
// grid: (S/64, H, B), 256 threads (8 warps: 2 in m x 4 in n)
#define SQS 196   // sQ/sK row stride (words): 196 % 32 = 4 -> conflict-free frag LDS
#define SVS 69    // sVt row stride
#define SPS 68    // sP row stride
__global__ __launch_bounds__(256, 1)
void attn_kernel(const float* __restrict__ Q,    // [BS, 3072]
                 const float* __restrict__ KN,   // [BS, 2048]
                 const float* __restrict__ KPE,  // [BS, 64]
                 const float* __restrict__ V,    // [BS, 2048]
                 float* __restrict__ O)          // [BS, 2048] (tf32-rounded out)
{
    extern __shared__ float smem[];
    float* sQ  = smem;                 // [64][196]
    float* sK  = sQ  + 64*SQS;         // [64][196]
    float* sVt = sK  + 64*SQS;         // [128][69]  (V transposed: [c][t])
    float* sP  = sVt + 128*SVS;        // [64][68]
    float* sM  = sP  + 64*SPS;         // [64]
    float* sL  = sM  + 64;             // [64]
    float* sAl = sL  + 64;             // [64]

    const int tid  = threadIdx.x;
    const int lane = tid & 31;
    const int warp = tid >> 5;
    const int g  = lane >> 2;
    const int tg = lane & 3;
    const int q0  = blockIdx.x * 64;
    const int h   = blockIdx.y;
    const int b   = blockIdx.z;
    const int bs0 = b * SS;

    const int warp_m  = (warp & 1) * 32;    // QK/PV m offset (2 frags of 16)
    const int warp_ns = (warp >> 1) * 16;   // QK n offset (2 frags of 8)
    const int warp_nv = (warp >> 1) * 32;   // PV n offset (4 frags of 8)

    // load Q tile [64][192] rounded
    for (int i = tid; i < 64*48; i += 256) {
        int r = i / 48, qq = i % 48;
        float4 v = *(const float4*)(Q + (size_t)(bs0 + q0 + r) * (HH*QK) + h*QK + qq*4);
        float* d = &sQ[r*SQS + qq*4];
        d[0] = tfr(v.x); d[1] = tfr(v.y); d[2] = tfr(v.z); d[3] = tfr(v.w);
    }
    if (tid < 64) { sM[tid] = NEG_BIG; sL[tid] = 0.f; }

    float oc[2][4][4];
    #pragma unroll
    for (int i = 0; i < 2; i++)
        #pragma unroll
        for (int j = 0; j < 4; j++)
            #pragma unroll
            for (int r = 0; r < 4; r++) oc[i][j][r] = 0.f;

    __syncthreads();

    const int ntiles = q0/64 + 1;
    for (int tt = 0; tt < ntiles; tt++) {
        const int t0 = tt * 64;
        // K tile [64][192] rounded
        for (int i = tid; i < 64*48; i += 256) {
            int t = i / 48, qq = i % 48;
            float4 v;
            if (qq < 32) v = *(const float4*)(KN  + (size_t)(bs0 + t0 + t) * (HH*NOPE) + h*NOPE + qq*4);
            else         v = *(const float4*)(KPE + (size_t)(bs0 + t0 + t) * ROPE + (qq-32)*4);
            float* d = &sK[t*SQS + qq*4];
            d[0] = tfr(v.x); d[1] = tfr(v.y); d[2] = tfr(v.z); d[3] = tfr(v.w);
        }
        // V tile transposed: sVt[c][t], rounded
        for (int i = tid; i < 64*32; i += 256) {
            int t = i >> 5, c4 = (i & 31) << 2;
            float4 v = *(const float4*)(V + (size_t)(bs0 + t0 + t) * (HH*VDIM) + h*VDIM + c4);
            sVt[(c4+0)*SVS + t] = tfr(v.x);
            sVt[(c4+1)*SVS + t] = tfr(v.y);
            sVt[(c4+2)*SVS + t] = tfr(v.z);
            sVt[(c4+3)*SVS + t] = tfr(v.w);
        }
        __syncthreads();

        // S = Q @ K^T via mma (64x64, k=192)
        float sc[2][2][4];
        #pragma unroll
        for (int i = 0; i < 2; i++)
            #pragma unroll
            for (int j = 0; j < 2; j++)
                #pragma unroll
                for (int r = 0; r < 4; r++) sc[i][j][r] = 0.f;

        #pragma unroll 4
        for (int k8 = 0; k8 < 192; k8 += 8) {
            uint32_t af[2][4], bf[2][2];
            #pragma unroll
            for (int im = 0; im < 2; im++) {
                int mb = warp_m + (im << 4);
                af[im][0] = __float_as_uint(sQ[(mb + g    )*SQS + k8 + tg]);
                af[im][1] = __float_as_uint(sQ[(mb + g + 8)*SQS + k8 + tg]);
                af[im][2] = __float_as_uint(sQ[(mb + g    )*SQS + k8 + tg + 4]);
                af[im][3] = __float_as_uint(sQ[(mb + g + 8)*SQS + k8 + tg + 4]);
            }
            #pragma unroll
            for (int in_ = 0; in_ < 2; in_++) {
                int nb = warp_ns + (in_ << 3);
                bf[in_][0] = __float_as_uint(sK[(nb + g)*SQS + k8 + tg]);
                bf[in_][1] = __float_as_uint(sK[(nb + g)*SQS + k8 + tg + 4]);
            }
            #pragma unroll
            for (int im = 0; im < 2; im++)
                #pragma unroll
                for (int in_ = 0; in_ < 2; in_++)
                    mma_tf32(sc[im][in_][0], sc[im][in_][1], sc[im][in_][2], sc[im][in_][3],
                             af[im][0], af[im][1], af[im][2], af[im][3],
                             bf[in_][0], bf[in_][1]);
        }

        // write scores (scaled, masked on diagonal tile) to sP
        const bool diag = (tt == ntiles - 1);
        #pragma unroll
        for (int im = 0; im < 2; im++) {
            int r0r = warp_m + (im << 4) + g;
            #pragma unroll
            for (int in_ = 0; in_ < 2; in_++) {
                int c0c = warp_ns + (in_ << 3) + tg*2;
                float v0 = sc[im][in_][0] * SCALE_C;
                float v1 = sc[im][in_][1] * SCALE_C;
                float v2 = sc[im][in_][2] * SCALE_C;
                float v3 = sc[im][in_][3] * SCALE_C;
                if (diag) {
                    if (c0c     > r0r    ) v0 = NEG_BIG;
                    if (c0c + 1 > r0r    ) v1 = NEG_BIG;
                    if (c0c     > r0r + 8) v2 = NEG_BIG;
                    if (c0c + 1 > r0r + 8) v3 = NEG_BIG;
                }
                sP[ r0r     *SPS + c0c    ] = v0;
                sP[ r0r     *SPS + c0c + 1] = v1;
                sP[(r0r + 8)*SPS + c0c    ] = v2;
                sP[(r0r + 8)*SPS + c0c + 1] = v3;
            }
        }
        __syncthreads();

        // online softmax: 4 threads per row, 16 cols each; store rounded exp
        {
            int r   = tid >> 2;
            int seg = tid & 3;
            float* prow = &sP[r*SPS + seg*16];
            float mx = NEG_BIG;
            #pragma unroll
            for (int j = 0; j < 16; j++) mx = fmaxf(mx, prow[j]);
            #pragma unroll
            for (int o = 1; o < 4; o <<= 1) mx = fmaxf(mx, __shfl_xor_sync(0xffffffffu, mx, o));
            float mold = sM[r];
            float mnew = fmaxf(mold, mx);
            float alpha = __expf(mold - mnew);
            float lsum = 0.f;
            #pragma unroll
            for (int j = 0; j < 16; j++) {
                float e = __expf(prow[j] - mnew);
                prow[j] = tfr(e);
                lsum += e;
            }
            #pragma unroll
            for (int o = 1; o < 4; o <<= 1) lsum += __shfl_xor_sync(0xffffffffu, lsum, o);
            if (seg == 0) { sM[r] = mnew; sL[r] = sL[r]*alpha + lsum; sAl[r] = alpha; }
        }
        __syncthreads();

        // rescale accumulators, then O += P @ V via mma (64x128, k=64)
        #pragma unroll
        for (int im = 0; im < 2; im++) {
            float al0 = sAl[warp_m + (im << 4) + g];
            float al8 = sAl[warp_m + (im << 4) + g + 8];
            #pragma unroll
            for (int in_ = 0; in_ < 4; in_++) {
                oc[im][in_][0] *= al0; oc[im][in_][1] *= al0;
                oc[im][in_][2] *= al8; oc[im][in_][3] *= al8;
            }
        }
        #pragma unroll
        for (int k8 = 0; k8 < 64; k8 += 8) {
            uint32_t af[2][4], bf[4][2];
            #pragma unroll
            for (int im = 0; im < 2; im++) {
                int mb = warp_m + (im << 4);
                af[im][0] = __float_as_uint(sP[(mb + g    )*SPS + k8 + tg]);
                af[im][1] = __float_as_uint(sP[(mb + g + 8)*SPS + k8 + tg]);
                af[im][2] = __float_as_uint(sP[(mb + g    )*SPS + k8 + tg + 4]);
                af[im][3] = __float_as_uint(sP[(mb + g + 8)*SPS + k8 + tg + 4]);
            }
            #pragma unroll
            for (int in_ = 0; in_ < 4; in_++) {
                int nb = warp_nv + (in_ << 3);
                bf[in_][0] = __float_as_uint(sVt[(nb + g)*SVS + k8 + tg]);
                bf[in_][1] = __float_as_uint(sVt[(nb + g)*SVS + k8 + tg + 4]);
            }
            #pragma unroll
            for (int im = 0; im < 2; im++)
                #pragma unroll
                for (int in_ = 0; in_ < 4; in_++)
                    mma_tf32(oc[im][in_][0], oc[im][in_][1], oc[im][in_][2], oc[im][in_][3],
                             af[im][0], af[im][1], af[im][2], af[im][3],
                             bf[in_][0], bf[in_][1]);
        }
        __syncthreads();
    }

    // epilogue: normalize, round to tf32, write
    #pragma unroll
    for (int im = 0; im < 2; im++) {
        int r0r = warp_m + (im << 4) + g;
        float inv0 = 1.f / sL[r0r];
        float inv8 = 1.f / sL[r0r + 8];
        #pragma unroll
        for (int in_ = 0; in_ < 4; in_++) {
            int col = warp_nv + (in_ << 3) + tg*2;
            float* p0 = &O[(size_t)(bs0 + q0 + r0r    ) * (HH*VDIM) + h*VDIM + col];
            float* p8 = &O[(size_t)(bs0 + q0 + r0r + 8) * (HH*VDIM) + h*VDIM + col];
            *(float2*)p0 = make_float2(tfr(oc[im][in_][0]*inv0), tfr(oc[im][in_][1]*inv0));
            *(float2*)p8 = make_float2(tfr(oc[im][in_][2]*inv8), tfr(oc[im][in_][3]*inv8));
        }
    }
}

// ---------------- launch ----------------
extern "C" void kernel_launch(void* const* d_in, const int* in_sizes, int n_in,
                              void* d_out, int out_size)
{
    const float* x      = (const float*)d_in[0];
    const float* wq     = (const float*)d_in[1];
    const float* wkv_a  = (const float*)d_in[2];
    const float* kvw    = (const float*)d_in[3];
    const float* wkv_b  = (const float*)d_in[4];
    const float* wo     = (const float*)d_in[5];
    const float* cosp   = (const float*)d_in[6];
    const float* sinp   = (const float*)d_in[7];
    float* out = (float*)d_out;

    float *Q, *KV, *CKV, *KPE, *KN, *V, *OH;
    float *Xr, *WQr, *WAr, *WBr, *WOr;
    cudaGetSymbolAddress((void**)&Q,   g_Q);
    cudaGetSymbolAddress((void**)&KV,  g_KV);
    cudaGetSymbolAddress((void**)&CKV, g_CKV);
    cudaGetSymbolAddress((void**)&KPE, g_KPE);
    cudaGetSymbolAddress((void**)&KN,  g_KN);
    cudaGetSymbolAddress((void**)&V,   g_V);
    cudaGetSymbolAddress((void**)&OH,  g_OH);
    cudaGetSymbolAddress((void**)&Xr,  g_Xr);
    cudaGetSymbolAddress((void**)&WQr, g_WQr);
    cudaGetSymbolAddress((void**)&WAr, g_WAr);
    cudaGetSymbolAddress((void**)&WBr, g_WBr);
    cudaGetSymbolAddress((void**)&WOr, g_WOr);

    const int ASMEM = (64*SQS*2 + 128*SVS + 64*SPS + 3*64) * 4;
    cudaFuncSetAttribute(attn_kernel, cudaFuncAttributeMaxDynamicSharedMemorySize, ASMEM);

    dim3 blk(256);
    const int BIGGRP = 1 << 30;

    // 0. pre-round operands to tf32
    {
        int n;
        n = BS*DIM/4;               round_tf32_kernel<<<(n+255)/256, 256>>>((const float4*)x,     (float4*)Xr,  n);
        n = (HH*QK)*DIM/4;          round_tf32_kernel<<<(n+255)/256, 256>>>((const float4*)wq,    (float4*)WQr, n);
        n = (KVR+ROPE)*DIM/4;       round_tf32_kernel<<<(n+255)/256, 256>>>((const float4*)wkv_a, (float4*)WAr, n);
        n = (HH*(NOPE+VDIM))*KVR/4; round_tf32_kernel<<<(n+255)/256, 256>>>((const float4*)wkv_b, (float4*)WBr, n);
        n = DIM*(HH*VDIM)/4;        round_tf32_kernel<<<(n+255)/256, 256>>>((const float4*)wo,    (float4*)WOr, n);
    }

    // 1. Q = X @ Wq^T                          [4096,3072]
    gemm_tf32<<<dim3(24, 32), blk>>>(Xr, WQr, Q, BS, HH*QK, DIM, BIGGRP, 0, 0);
    // 2. rope q_pe in place
    rope_q_kernel<<<(BS*HH*32 + 255)/256, 256>>>(Q, cosp, sinp);
    // 3. KV = X @ Wkv_a^T                      [4096,576]
    gemm_tf32<<<dim3(5, 32), blk>>>(Xr, WAr, KV, BS, KVR+ROPE, DIM, BIGGRP, 0, 0);
    // 4. rmsnorm + rope(k_pe)
    kv_post_kernel<<<BS, 128>>>(KV, kvw, cosp, sinp, CKV, KPE);
    // 5. k_nope = CKV @ wb_k^T
    gemm_tf32<<<dim3(16, 32), blk>>>(CKV, WBr, KN, BS, HH*NOPE, KVR, 128, 256, 0);
    // 6. v = CKV @ wb_v^T
    gemm_tf32<<<dim3(16, 32), blk>>>(CKV, WBr, V, BS, HH*VDIM, KVR, 128, 256, 128);
    // 7. attention
    attn_kernel<<<dim3(SS/64, HH, BB), 256, ASMEM>>>(Q, KN, KPE, V, OH);
    // 8. out = OH @ wo^T
    gemm_tf32<<<dim3(16, 32), blk>>>(OH, WOr, out, BS, DIM, HH*VDIM, BIGGRP, 0, 0);
}

// round 8
// speedup vs baseline: 4.7961x; 1.5304x over previous
#include <cuda_runtime.h>
#include <cuda_bf16.h>
#include <math.h>
#include <stdint.h>

// Arch-specific feature gate: tcgen05 only exists in the sm_103a-specific pass.
#if defined(__CUDA_ARCH__) && (defined(__CUDA_ARCH_FEAT_SM103_ALL) || (defined(__CUDA_ARCH_SPECIFIC__) && (__CUDA_ARCH_SPECIFIC__ == 1030)))
#define T5_OK 1
#else
#define T5_OK 0
#endif

// Problem constants
#define BB 2
#define SS 2048
#define DIM 2048
#define HH 16
#define KVR 512
#define NOPE 128
#define ROPE 64
#define VDIM 128
#define QK 192
#define BS (BB*SS)           // 4096
#define SCALE_C 0.07216878364870322f   // 192^-0.5
#define NEG_BIG -1e30f

// ---------------- fp32 scratch ----------------
__device__ float g_Q  [(size_t)BS * (HH*QK)];
__device__ float g_KV [(size_t)BS * (KVR+ROPE)];
__device__ float g_CKV[(size_t)BS * KVR];          // fallback path
__device__ float g_KPE[(size_t)BS * ROPE];
__device__ float g_KN [(size_t)BS * (HH*NOPE)];
__device__ float g_V  [(size_t)BS * (HH*VDIM)];
__device__ float g_OH [(size_t)BS * (HH*VDIM)];    // fallback path
// fallback tf32-rounded copies
__device__ float g_Xr [(size_t)BS * DIM];
__device__ float g_WQr[(size_t)(HH*QK) * DIM];
__device__ float g_WAr[(size_t)(KVR+ROPE) * DIM];
__device__ float g_WBr[(size_t)(HH*(NOPE+VDIM)) * KVR];
__device__ float g_WOr[(size_t)DIM * (HH*VDIM)];

// ---------------- bf16 split panel scratch (tcgen05 path) ----------------
#define APAN 8192
#define BPAN 16384
__device__ __align__(1024) __nv_bfloat16 g_Xh [(size_t)32*32*APAN],  g_Xl [(size_t)32*32*APAN];
__device__ __align__(1024) __nv_bfloat16 g_WQh[(size_t)12*32*BPAN],  g_WQl[(size_t)12*32*BPAN];
__device__ __align__(1024) __nv_bfloat16 g_WAh[(size_t)3*32*BPAN],   g_WAl[(size_t)3*32*BPAN];
__device__ __align__(1024) __nv_bfloat16 g_WBkh[(size_t)8*8*BPAN],   g_WBkl[(size_t)8*8*BPAN];
__device__ __align__(1024) __nv_bfloat16 g_WBvh[(size_t)8*8*BPAN],   g_WBvl[(size_t)8*8*BPAN];
__device__ __align__(1024) __nv_bfloat16 g_WOh[(size_t)8*32*BPAN],   g_WOl[(size_t)8*32*BPAN];
__device__ __align__(1024) __nv_bfloat16 g_CKVh[(size_t)32*8*APAN],  g_CKVl[(size_t)32*8*APAN];
__device__ __align__(1024) __nv_bfloat16 g_OHh[(size_t)32*32*APAN],  g_OHl[(size_t)32*32*APAN];

// ---------------- helpers ----------------
__device__ __forceinline__ uint32_t f2tf32(float x) {
    uint32_t r; asm("cvt.rna.tf32.f32 %0, %1;" : "=r"(r) : "f"(x)); return r;
}
__device__ __forceinline__ float tfr(float x) { return __uint_as_float(f2tf32(x)); }

__device__ __forceinline__ void mma_tf32(float& c0, float& c1, float& c2, float& c3,
                                         uint32_t a0, uint32_t a1, uint32_t a2, uint32_t a3,
                                         uint32_t b0, uint32_t b1)
{
    asm volatile(
        "mma.sync.aligned.m16n8k8.row.col.f32.tf32.tf32.f32 "
        "{%0,%1,%2,%3}, {%4,%5,%6,%7}, {%8,%9}, {%0,%1,%2,%3};\n"
        : "+f"(c0), "+f"(c1), "+f"(c2), "+f"(c3)
        : "r"(a0), "r"(a1), "r"(a2), "r"(a3), "r"(b0), "r"(b1));
}

__device__ __forceinline__ void cp_async16(uint32_t saddr, const void* gptr, int src_bytes) {
    asm volatile("cp.async.cg.shared.global [%0], [%1], 16, %2;\n"
                 :: "r"(saddr), "l"(gptr), "r"(src_bytes));
}
__device__ __forceinline__ void cp_commit() { asm volatile("cp.async.commit_group;\n"); }
template<int N> __device__ __forceinline__ void cp_wait() {
    asm volatile("cp.async.wait_group %0;\n" :: "n"(N));
}
__device__ __forceinline__ uint32_t swz(uint32_t off) { return off ^ ((off >> 3) & 0x70); }

#if T5_OK
__device__ __forceinline__ uint32_t smem_u32(const void* p) {
    uint32_t a;
    asm("{ .reg .u64 t; cvta.to.shared.u64 t, %1; cvt.u32.u64 %0, t; }" : "=r"(a) : "l"(p));
    return a;
}
__device__ __forceinline__ uint32_t elect_one() {
    uint32_t p;
    asm volatile("{\n\t.reg .pred p;\n\telect.sync _|p, 0xFFFFFFFF;\n\tselp.b32 %0, 1, 0, p;\n\t}" : "=r"(p));
    return p;
}
__device__ __forceinline__ void mbar_init(uint32_t a, uint32_t n) {
    asm volatile("mbarrier.init.shared.b64 [%0], %1;" :: "r"(a), "r"(n) : "memory");
}
__device__ __forceinline__ void mbar_inval(uint32_t a) {
    asm volatile("mbarrier.inval.shared.b64 [%0];" :: "r"(a) : "memory");
}
__device__ __forceinline__ void mbar_expect_tx(uint32_t a, uint32_t bytes) {
    asm volatile("mbarrier.arrive.expect_tx.shared.b64 _, [%0], %1;" :: "r"(a), "r"(bytes) : "memory");
}
__device__ __forceinline__ void mbar_wait(uint32_t a, uint32_t parity) {
    asm volatile(
        "{\n\t.reg .pred P;\n\t"
        "W_%=:\n\t"
        "mbarrier.try_wait.parity.acquire.cta.shared::cta.b64 P, [%0], %1, 0x989680;\n\t"
        "@P bra.uni D_%=;\n\t"
        "bra.uni W_%=;\n\t"
        "D_%=:\n\t}"
        :: "r"(a), "r"(parity) : "memory");
}
__device__ __forceinline__ void bulk_g2s(uint32_t dst, const void* src, uint32_t bytes, uint32_t mbar) {
    asm volatile(
        "cp.async.bulk.shared::cta.global.mbarrier::complete_tx::bytes [%0], [%1], %2, [%3];"
        :: "r"(dst), "l"(src), "r"(bytes), "r"(mbar) : "memory");
}
__device__ __forceinline__ void t5_alloc(uint32_t smem_res, uint32_t ncols) {
    asm volatile("tcgen05.alloc.cta_group::1.sync.aligned.shared::cta.b32 [%0], %1;"
                 :: "r"(smem_res), "r"(ncols) : "memory");
}
__device__ __forceinline__ void t5_dealloc(uint32_t tmem, uint32_t ncols) {
    asm volatile("tcgen05.dealloc.cta_group::1.sync.aligned.b32 %0, %1;" :: "r"(tmem), "r"(ncols));
}
__device__ __forceinline__ void t5_commit(uint32_t mbar) {
    asm volatile("tcgen05.commit.cta_group::1.mbarrier::arrive::one.shared::cluster.b64 [%0];"
                 :: "r"(mbar) : "memory");
}
__device__ __forceinline__ void t5_fence_after() {
    asm volatile("tcgen05.fence::after_thread_sync;" ::: "memory");
}
__device__ __forceinline__ void t5_wait_ld() {
    asm volatile("tcgen05.wait::ld.sync.aligned;" ::: "memory");
}
__device__ __forceinline__ void t5_mma_f16_ss(uint32_t d, uint64_t ad, uint64_t bd,
                                              uint32_t idesc, uint32_t en) {
    asm volatile(
        "{\n\t.reg .pred p;\n\t"
        "setp.ne.u32 p, %4, 0;\n\t"
        "tcgen05.mma.cta_group::1.kind::f16 [%0], %1, %2, %3, {%5,%5,%5,%5}, p;\n\t}"
        :: "r"(d), "l"(ad), "l"(bd), "r"(idesc), "r"(en), "r"(0u) : "memory");
}
static __device__ __forceinline__ uint64_t mk_desc(uint32_t addr) {
    const uint64_t base = (uint64_t(2) << 61) | (uint64_t(1) << 46)
                        | (uint64_t(64) << 32) | (uint64_t(1) << 16);
    return base | ((uint64_t)(addr >> 4) & 0x3FFF);
}
#define T5_IDESC ((1u<<4)|(1u<<7)|(1u<<10)|((256u/8u)<<17)|((128u/16u)<<24))
#endif  // T5_OK

// ---------------- preprocessing kernels ----------------
__global__ void round_tf32_kernel(const float4* __restrict__ src, float4* __restrict__ dst, int n4)
{
#if !T5_OK
    int i = blockIdx.x * blockDim.x + threadIdx.x;
    if (i >= n4) return;
    float4 v = src[i];
    v.x = tfr(v.x); v.y = tfr(v.y); v.z = tfr(v.z); v.w = tfr(v.w);
    dst[i] = v;
#endif
}

__global__ void split_A_kernel(const float* __restrict__ src,
                               __nv_bfloat16* __restrict__ dh, __nv_bfloat16* __restrict__ dl,
                               int K, int nchunks)
{
#if T5_OK
    size_t i = (size_t)blockIdx.x * 256 + threadIdx.x;
    if (i >= (size_t)BS * K) return;
    int row = (int)(i / K), k = (int)(i % K);
    float v = src[i];
    int tile = row >> 7, rin = row & 127, chunk = k >> 6, cin = k & 63;
    uint32_t sw = swz((uint32_t)(rin * 128 + cin * 2));
    size_t idx = ((size_t)(tile * nchunks + chunk) << 13) + (sw >> 1);
    __nv_bfloat16 h = __float2bfloat16(v);
    dh[idx] = h;
    dl[idx] = __float2bfloat16(v - __bfloat162float(h));
#endif
}

__global__ void split_B_kernel(const float* __restrict__ src,
                               __nv_bfloat16* __restrict__ dh, __nv_bfloat16* __restrict__ dl,
                               int Nrows, int K, int group, int gstride, int gbase, size_t total)
{
#if T5_OK
    size_t i = (size_t)blockIdx.x * 256 + threadIdx.x;
    if (i >= total) return;
    int n = (int)(i / K), k = (int)(i % K);
    float v = 0.f;
    if (n < Nrows) {
        int br = gbase + (n / group) * gstride + (n % group);
        v = src[(size_t)br * K + k];
    }
    int tile = n >> 8, rin = n & 255, chunk = k >> 6, cin = k & 63;
    int nchunks = K >> 6;
    uint32_t sw = swz((uint32_t)(rin * 128 + cin * 2));
    size_t idx = ((size_t)(tile * nchunks + chunk) << 14) + (sw >> 1);
    __nv_bfloat16 h = __float2bfloat16(v);
    dh[idx] = h;
    dl[idx] = __float2bfloat16(v - __bfloat162float(h));
#endif
}

// ---------------- fallback tf32 GEMM (R3, proven) ----------------
#define NST 3
__global__ __launch_bounds__(256)
void gemm_tf32(const float* __restrict__ A, const float* __restrict__ B,
               float* __restrict__ C, int M, int N, int K,
               int group, int gstride, int gbase)
{
#if !T5_OK
    __shared__ uint32_t As[NST][128][20];
    __shared__ uint32_t Bs[NST][128][20];

    const int tid  = threadIdx.x;
    const int lane = tid & 31;
    const int warp = tid >> 5;
    const int row0 = blockIdx.y * 128;
    const int col0 = blockIdx.x * 128;

    const int warp_m = (warp & 1) * 64;
    const int warp_n = (warp >> 1) * 32;
    const int g  = lane >> 2;
    const int tg = lane & 3;

    int r0q = (tid) >> 2,        kq0 = (tid & 3) << 2;
    int r1q = (tid + 256) >> 2,  kq1 = ((tid + 256) & 3) << 2;

    const float* A0 = A + (size_t)(row0 + r0q) * K + kq0;
    const float* A1 = A + (size_t)(row0 + r1q) * K + kq1;

    int bn0 = col0 + r0q, bn1 = col0 + r1q;
    int bok0 = (bn0 < N) ? 16 : 0;
    int bok1 = (bn1 < N) ? 16 : 0;
    int br0 = bok0 ? (gbase + (bn0 / group) * gstride + (bn0 % group)) : 0;
    int br1 = bok1 ? (gbase + (bn1 / group) * gstride + (bn1 % group)) : 0;
    const float* B0 = B + (size_t)br0 * K + kq0;
    const float* B1 = B + (size_t)br1 * K + kq1;

    uint32_t sa0[NST], sa1[NST], sb0[NST], sb1[NST];
    #pragma unroll
    for (int s = 0; s < NST; s++) {
        sa0[s] = (uint32_t)__cvta_generic_to_shared(&As[s][r0q][kq0]);
        sa1[s] = (uint32_t)__cvta_generic_to_shared(&As[s][r1q][kq1]);
        sb0[s] = (uint32_t)__cvta_generic_to_shared(&Bs[s][r0q][kq0]);
        sb1[s] = (uint32_t)__cvta_generic_to_shared(&Bs[s][r1q][kq1]);
    }

    float acc[4][4][4];
    #pragma unroll
    for (int i = 0; i < 4; i++)
        #pragma unroll
        for (int j = 0; j < 4; j++)
            #pragma unroll
            for (int r = 0; r < 4; r++) acc[i][j][r] = 0.f;

    const int nk = K >> 4;

    #pragma unroll
    for (int s = 0; s < NST - 1; s++) {
        int ko = s << 4;
        cp_async16(sa0[s], A0 + ko, 16);
        cp_async16(sa1[s], A1 + ko, 16);
        cp_async16(sb0[s], B0 + ko, bok0);
        cp_async16(sb1[s], B1 + ko, bok1);
        cp_commit();
    }

    for (int kt = 0; kt < nk; kt++) {
        const int st = kt % NST;
        cp_wait<NST - 2>();
        __syncthreads();

        #pragma unroll
        for (int kk = 0; kk < 16; kk += 8) {
            uint32_t af[4][4], bf[4][2];
            #pragma unroll
            for (int im = 0; im < 4; im++) {
                int mb = warp_m + (im << 4);
                af[im][0] = As[st][mb + g    ][kk + tg];
                af[im][1] = As[st][mb + g + 8][kk + tg];
                af[im][2] = As[st][mb + g    ][kk + tg + 4];
                af[im][3] = As[st][mb + g + 8][kk + tg + 4];
            }
            #pragma unroll
            for (int in_ = 0; in_ < 4; in_++) {
                int nb = warp_n + (in_ << 3);
                bf[in_][0] = Bs[st][nb + g][kk + tg];
                bf[in_][1] = Bs[st][nb + g][kk + tg + 4];
            }
            #pragma unroll
            for (int im = 0; im < 4; im++)
                #pragma unroll
                for (int in_ = 0; in_ < 4; in_++)
                    mma_tf32(acc[im][in_][0], acc[im][in_][1], acc[im][in_][2], acc[im][in_][3],
                             af[im][0], af[im][1], af[im][2], af[im][3],
                             bf[in_][0], bf[in_][1]);
        }
        __syncthreads();

        int knext = kt + NST - 1;
        if (knext < nk) {
            int sn = knext % NST;
            int ko = knext << 4;
            cp_async16(sa0[sn], A0 + ko, 16);
            cp_async16(sa1[sn], A1 + ko, 16);
            cp_async16(sb0[sn], B0 + ko, bok0);
            cp_async16(sb1[sn], B1 + ko, bok1);
        }
        cp_commit();
    }

    #pragma unroll
    for (int im = 0; im < 4; im++) {
        #pragma unroll
        for (int in_ = 0; in_ < 4; in_++) {
            int row = row0 + warp_m + (im << 4) + g;
            int col = col0 + warp_n + (in_ << 3) + tg * 2;
            if (col < N) {
                *(float2*)(C + (size_t)row * N + col) =
                    make_float2(acc[im][in_][0], acc[im][in_][1]);
                *(float2*)(C + (size_t)(row + 8) * N + col) =
                    make_float2(acc[im][in_][2], acc[im][in_][3]);
            }
        }
    }
#endif
}

// ---------------- tcgen05 bf16x3 GEMM ----------------
#define SM_TMPTR 0
#define SM_FULL0 16
#define SM_FREE0 32
#define SM_DONE  48
#define SM_STG0  1024
#define STG_BYTES 98304
#define OFF_AH 0
#define OFF_AL 16384
#define OFF_BH 32768
#define OFF_BL 65536
#define GEMM_SMEM (1024 + 2*STG_BYTES)

__global__ __launch_bounds__(128, 1)
void gemm_t5(const __nv_bfloat16* __restrict__ Ah, const __nv_bfloat16* __restrict__ Al,
             const __nv_bfloat16* __restrict__ Bh, const __nv_bfloat16* __restrict__ Bl,
             float* __restrict__ C, int N, int nchunks)
{
#if T5_OK
    extern __shared__ __align__(1024) char smraw[];
    const uint32_t smb = smem_u32(smraw);
    const int tid  = threadIdx.x;
    const int warp = tid >> 5;
    const int lane = tid & 31;
    const int tile_n = blockIdx.x;
    const int tile_m = blockIdx.y;

    if (tid == 0) {
        mbar_init(smb + SM_FULL0 + 0, 1);
        mbar_init(smb + SM_FULL0 + 8, 1);
        mbar_init(smb + SM_FREE0 + 0, 1);
        mbar_init(smb + SM_FREE0 + 8, 1);
        mbar_init(smb + SM_DONE, 1);
    }
    if (warp == 1) t5_alloc(smb + SM_TMPTR, 512);
    __syncthreads();
    uint32_t tmem;
    asm volatile("ld.shared.b32 %0, [%1];" : "=r"(tmem) : "r"(smb + SM_TMPTR));

    if (warp == 0) {
        if (elect_one()) {
            uint32_t pph = 1;
            const size_t abase = (size_t)tile_m * nchunks;
            const size_t bbase = (size_t)tile_n * nchunks;
            for (int c = 0; c < nchunks; c++) {
                int s = c & 1;
                uint32_t stg = smb + SM_STG0 + s * STG_BYTES;
                mbar_wait(smb + SM_FREE0 + s * 8, pph);
                mbar_expect_tx(smb + SM_FULL0 + s * 8, STG_BYTES);
                bulk_g2s(stg + OFF_AH, Ah + (abase + c) * APAN, 16384, smb + SM_FULL0 + s * 8);
                bulk_g2s(stg + OFF_AL, Al + (abase + c) * APAN, 16384, smb + SM_FULL0 + s * 8);
                bulk_g2s(stg + OFF_BH, Bh + (bbase + c) * BPAN, 32768, smb + SM_FULL0 + s * 8);
                bulk_g2s(stg + OFF_BL, Bl + (bbase + c) * BPAN, 32768, smb + SM_FULL0 + s * 8);
                if (s == 1) pph ^= 1;
            }
        }
    }
    if (warp == 1) {
        if (elect_one()) {
            uint32_t cph = 0;
            for (int c = 0; c < nchunks; c++) {
                int s = c & 1;
                uint32_t stg = smb + SM_STG0 + s * STG_BYTES;
                mbar_wait(smb + SM_FULL0 + s * 8, cph);
                uint64_t ahd = mk_desc(stg + OFF_AH);
                uint64_t ald = mk_desc(stg + OFF_AL);
                uint64_t bhd = mk_desc(stg + OFF_BH);
                uint64_t bld = mk_desc(stg + OFF_BL);
                uint64_t ads[3] = {ahd, ahd, ald};
                uint64_t bds[3] = {bhd, bld, bhd};
                #pragma unroll
                for (int p = 0; p < 3; p++) {
                    #pragma unroll
                    for (int k = 0; k < 4; k++) {
                        uint32_t en = (c | p | k) ? 1u : 0u;
                        t5_mma_f16_ss(tmem, ads[p] + k * 2, bds[p] + k * 2, T5_IDESC, en);
                    }
                }
                t5_commit(smb + SM_FREE0 + s * 8);
                if (c == nchunks - 1) t5_commit(smb + SM_DONE);
                if (s == 1) cph ^= 1;
            }
        }
    }

    mbar_wait(smb + SM_DONE, 0);
    t5_fence_after();

    const int gr = (tile_m << 7) + (warp << 5) + lane;
    #pragma unroll 1
    for (int cb = 0; cb < 8; cb++) {
        uint32_t d[32];
        asm volatile(
            "tcgen05.ld.sync.aligned.32x32b.x32.b32 "
            "{%0, %1, %2, %3, %4, %5, %6, %7, "
            " %8, %9, %10, %11, %12, %13, %14, %15, "
            " %16, %17, %18, %19, %20, %21, %22, %23, "
            " %24, %25, %26, %27, %28, %29, %30, %31}, [%32];"
            : "=r"(d[0]),  "=r"(d[1]),  "=r"(d[2]),  "=r"(d[3]),
              "=r"(d[4]),  "=r"(d[5]),  "=r"(d[6]),  "=r"(d[7]),
              "=r"(d[8]),  "=r"(d[9]),  "=r"(d[10]), "=r"(d[11]),
              "=r"(d[12]), "=r"(d[13]), "=r"(d[14]), "=r"(d[15]),
              "=r"(d[16]), "=r"(d[17]), "=r"(d[18]), "=r"(d[19]),
              "=r"(d[20]), "=r"(d[21]), "=r"(d[22]), "=r"(d[23]),
              "=r"(d[24]), "=r"(d[25]), "=r"(d[26]), "=r"(d[27]),
              "=r"(d[28]), "=r"(d[29]), "=r"(d[30]), "=r"(d[31])
            : "r"(tmem + cb * 32));
        t5_wait_ld();
        int gc0 = (tile_n << 8) + (cb << 5);
        float* cp = C + (size_t)gr * N + gc0;
        #pragma unroll
        for (int j = 0; j < 32; j += 4) {
            if (gc0 + j < N)
                *(float4*)(cp + j) = make_float4(__uint_as_float(d[j]),   __uint_as_float(d[j+1]),
                                                 __uint_as_float(d[j+2]), __uint_as_float(d[j+3]));
        }
    }

    __syncthreads();
    if (tid == 0) {
        mbar_inval(smb + SM_FULL0 + 0); mbar_inval(smb + SM_FULL0 + 8);
        mbar_inval(smb + SM_FREE0 + 0); mbar_inval(smb + SM_FREE0 + 8);
        mbar_inval(smb + SM_DONE);
    }
    if (warp == 1) t5_dealloc(tmem, 512);
#endif
}

// ---------------- RoPE on q_pe part of Q (in place) ----------------
__global__ void rope_q_kernel(float* __restrict__ Q,
                              const float* __restrict__ COS,
                              const float* __restrict__ SIN)
{
    int idx = blockIdx.x * blockDim.x + threadIdx.x;
    if (idx >= BS * HH * 32) return;
    int i = idx & 31;
    int h = (idx >> 5) & 15;
    int m = idx >> 9;
    int s = m & (SS - 1);
    size_t base = (size_t)m * (HH*QK) + h * QK + NOPE + 2*i;
    float xe = Q[base], xo = Q[base + 1];
    float c  = COS[s*32 + i], sn = SIN[s*32 + i];
    Q[base]     = xe*c - xo*sn;
    Q[base + 1] = xe*sn + xo*c;
}

// ---------------- KV post ----------------
__global__ void kv_post_kernel(const float* __restrict__ KV,
                               const float* __restrict__ W,
                               const float* __restrict__ COS,
                               const float* __restrict__ SIN,
                               float* __restrict__ CKV,
                               __nv_bfloat16* __restrict__ CKVh,
                               __nv_bfloat16* __restrict__ CKVl,
                               float* __restrict__ KPE)
{
    __shared__ float red[4];
    __shared__ float rs_s;
    const int m = blockIdx.x;
    const int tid = threadIdx.x; // 128 threads
    const float* row = KV + (size_t)m * (KVR+ROPE);

    float ss = 0.f;
    for (int c = tid; c < KVR; c += 128) { float v = row[c]; ss += v * v; }
    #pragma unroll
    for (int o = 16; o; o >>= 1) ss += __shfl_xor_sync(0xffffffffu, ss, o);
    if ((tid & 31) == 0) red[tid >> 5] = ss;
    __syncthreads();
    if (tid == 0) {
        float t = red[0] + red[1] + red[2] + red[3];
        rs_s = rsqrtf(t / (float)KVR + 1e-6f);
    }
    __syncthreads();
    float rs = rs_s;
#if T5_OK
    const int tile = m >> 7, rin = m & 127;
    for (int c = tid; c < KVR; c += 128) {
        float v = row[c] * rs * W[c];
        int chunk = c >> 6, cin = c & 63;
        uint32_t sw = swz((uint32_t)(rin * 128 + cin * 2));
        size_t idx = ((size_t)(tile * 8 + chunk) << 13) + (sw >> 1);
        __nv_bfloat16 h = __float2bfloat16(v);
        CKVh[idx] = h;
        CKVl[idx] = __float2bfloat16(v - __bfloat162float(h));
    }
#else
    for (int c = tid; c < KVR; c += 128)
        CKV[(size_t)m * KVR + c] = tfr(row[c] * rs * W[c]);
#endif

    if (tid < 32) {
        int i = tid;
        int s = m & (SS - 1);
        float xe = row[KVR + 2*i], xo = row[KVR + 2*i + 1];
        float c  = COS[s*32 + i], sn = SIN[s*32 + i];
        KPE[(size_t)m * ROPE + 2*i]     = xe*c - xo*sn;
        KPE[(size_t)m * ROPE + 2*i + 1] = xe*sn + xo*c;
    }
}

// ---------------- flash attention (tf32 mma) ----------------
#define SQS 196
#define SVS 69
#define SPS 68
__global__ __launch_bounds__(256, 1)
void attn_kernel(const float* __restrict__ Q,
                 const float* __restrict__ KN,
                 const float* __restrict__ KPE,
                 const float* __restrict__ V,
                 float* __restrict__ OH,
                 __nv_bfloat16* __restrict__ OHh,
                 __nv_bfloat16* __restrict__ OHl)
{
    extern __shared__ float smem[];
    float* sQ  = smem;
    float* sK  = sQ  + 64*SQS;
    float* sVt = sK  + 64*SQS;
    float* sP  = sVt + 128*SVS;
    float* sM  = sP  + 64*SPS;
    float* sL  = sM  + 64;
    float* sAl = sL  + 64;

    const int tid  = threadIdx.x;
    const int lane = tid & 31;
    const int warp = tid >> 5;
    const int g  = lane >> 2;
    const int tg = lane & 3;
    const int q0  = blockIdx.x * 64;
    const int h   = blockIdx.y;
    const int b   = blockIdx.z;
    const int bs0 = b * SS;

    const int warp_m  = (warp & 1) * 32;
    const int warp_ns = (warp >> 1) * 16;
    const int warp_nv = (warp >> 1) * 32;

    for (int i = tid; i < 64*48; i += 256) {
        int r = i / 48, qq = i % 48;
        float4 v = *(const float4*)(Q + (size_t)(bs0 + q0 + r) * (HH*QK) + h*QK + qq*4);
        float* d = &sQ[r*SQS + qq*4];
        d[0] = tfr(v.x); d[1] = tfr(v.y); d[2] = tfr(v.z); d[3] = tfr(v.w);
    }
    if (tid < 64) { sM[tid] = NEG_BIG; sL[tid] = 0.f; }

    float oc[2][4][4];
    #pragma unroll
    for (int i = 0; i < 2; i++)
        #pragma unroll
        for (int j = 0; j < 4; j++)
            #pragma unroll
            for (int r = 0; r < 4; r++) oc[i][j][r] = 0.f;

    __syncthreads();

    const int ntiles = q0/64 + 1;
    for (int tt = 0; tt < ntiles; tt++) {
        const int t0 = tt * 64;
        for (int i = tid; i < 64*48; i += 256) {
            int t = i / 48, qq = i % 48;
            float4 v;
            if (qq < 32) v = *(const float4*)(KN  + (size_t)(bs0 + t0 + t) * (HH*NOPE) + h*NOPE + qq*4);
            else         v = *(const float4*)(KPE + (size_t)(bs0 + t0 + t) * ROPE + (qq-32)*4);
            float* d = &sK[t*SQS + qq*4];
            d[0] = tfr(v.x); d[1] = tfr(v.y); d[2] = tfr(v.z); d[3] = tfr(v.w);
        }
        for (int i = tid; i < 64*32; i += 256) {
            int t = i >> 5, c4 = (i & 31) << 2;
            float4 v = *(const float4*)(V + (size_t)(bs0 + t0 + t) * (HH*VDIM) + h*VDIM + c4);
            sVt[(c4+0)*SVS + t] = tfr(v.x);
            sVt[(c4+1)*SVS + t] = tfr(v.y);
            sVt[(c4+2)*SVS + t] = tfr(v.z);
            sVt[(c4+3)*SVS + t] = tfr(v.w);
        }
        __syncthreads();

        float sc[2][2][4];
        #pragma unroll
        for (int i = 0; i < 2; i++)
            #pragma unroll
            for (int j = 0; j < 2; j++)
                #pragma unroll
                for (int r = 0; r < 4; r++) sc[i][j][r] = 0.f;

        #pragma unroll 4
        for (int k8 = 0; k8 < 192; k8 += 8) {
            uint32_t af[2][4], bf[2][2];
            #pragma unroll
            for (int im = 0; im < 2; im++) {
                int mb = warp_m + (im << 4);
                af[im][0] = __float_as_uint(sQ[(mb + g    )*SQS + k8 + tg]);
                af[im][1] = __float_as_uint(sQ[(mb + g + 8)*SQS + k8 + tg]);
                af[im][2] = __float_as_uint(sQ[(mb + g    )*SQS + k8 + tg + 4]);
                af[im][3] = __float_as_uint(sQ[(mb + g + 8)*SQS + k8 + tg + 4]);
            }
            #pragma unroll
            for (int in_ = 0; in_ < 2; in_++) {
                int nb = warp_ns + (in_ << 3);
                bf[in_][0] = __float_as_uint(sK[(nb + g)*SQS + k8 + tg]);
                bf[in_][1] = __float_as_uint(sK[(nb + g)*SQS + k8 + tg + 4]);
            }
            #pragma unroll
            for (int im = 0; im < 2; im++)
                #pragma unroll
                for (int in_ = 0; in_ < 2; in_++)
                    mma_tf32(sc[im][in_][0], sc[im][in_][1], sc[im][in_][2], sc[im][in_][3],
                             af[im][0], af[im][1], af[im][2], af[im][3],
                             bf[in_][0], bf[in_][1]);
        }

        const bool diag = (tt == ntiles - 1);
        #pragma unroll
        for (int im = 0; im < 2; im++) {
            int r0r = warp_m + (im << 4) + g;
            #pragma unroll
            for (int in_ = 0; in_ < 2; in_++) {
                int c0c = warp_ns + (in_ << 3) + tg*2;
                float v0 = sc[im][in_][0] * SCALE_C;
                float v1 = sc[im][in_][1] * SCALE_C;
                float v2 = sc[im][in_][2] * SCALE_C;
                float v3 = sc[im][in_][3] * SCALE_C;
                if (diag) {
                    if (c0c     > r0r    ) v0 = NEG_BIG;
                    if (c0c + 1 > r0r    ) v1 = NEG_BIG;
                    if (c0c     > r0r + 8) v2 = NEG_BIG;
                    if (c0c + 1 > r0r + 8) v3 = NEG_BIG;
                }
                sP[ r0r     *SPS + c0c    ] = v0;
                sP[ r0r     *SPS + c0c + 1] = v1;
                sP[(r0r + 8)*SPS + c0c    ] = v2;
                sP[(r0r + 8)*SPS + c0c + 1] = v3;
            }
        }
        __syncthreads();

        {
            int r   = tid >> 2;
            int seg = tid & 3;
            float* prow = &sP[r*SPS + seg*16];
            float mx = NEG_BIG;
            #pragma unroll
            for (int j = 0; j < 16; j++) mx = fmaxf(mx, prow[j]);
            #pragma unroll
            for (int o = 1; o < 4; o <<= 1) mx = fmaxf(mx, __shfl_xor_sync(0xffffffffu, mx, o));
            float mold = sM[r];
            float mnew = fmaxf(mold, mx);
            float alpha = __expf(mold - mnew);
            float lsum = 0.f;
            #pragma unroll
            for (int j = 0; j < 16; j++) {
                float e = __expf(prow[j] - mnew);
                prow[j] = tfr(e);
                lsum += e;
            }
            #pragma unroll
            for (int o = 1; o < 4; o <<= 1) lsum += __shfl_xor_sync(0xffffffffu, lsum, o);
            if (seg == 0) { sM[r] = mnew; sL[r] = sL[r]*alpha + lsum; sAl[r] = alpha; }
        }
        __syncthreads();

        #pragma unroll
        for (int im = 0; im < 2; im++) {
            float al0 = sAl[warp_m + (im << 4) + g];
            float al8 = sAl[warp_m + (im << 4) + g + 8];
            #pragma unroll
            for (int in_ = 0; in_ < 4; in_++) {
                oc[im][in_][0] *= al0; oc[im][in_][1] *= al0;
                oc[im][in_][2] *= al8; oc[im][in_][3] *= al8;
            }
        }
        #pragma unroll
        for (int k8 = 0; k8 < 64; k8 += 8) {
            uint32_t af[2][4], bf[4][2];
            #pragma unroll
            for (int im = 0; im < 2; im++) {
                int mb = warp_m + (im << 4);
                af[im][0] = __float_as_uint(sP[(mb + g    )*SPS + k8 + tg]);
                af[im][1] = __float_as_uint(sP[(mb + g + 8)*SPS + k8 + tg]);
                af[im][2] = __float_as_uint(sP[(mb + g    )*SPS + k8 + tg + 4]);
                af[im][3] = __float_as_uint(sP[(mb + g + 8)*SPS + k8 + tg + 4]);
            }
            #pragma unroll
            for (int in_ = 0; in_ < 4; in_++) {
                int nb = warp_nv + (in_ << 3);
                bf[in_][0] = __float_as_uint(sVt[(nb + g)*SVS + k8 + tg]);
                bf[in_][1] = __float_as_uint(sVt[(nb + g)*SVS + k8 + tg + 4]);
            }
            #pragma unroll
            for (int im = 0; im < 2; im++)
                #pragma unroll
                for (int in_ = 0; in_ < 4; in_++)
                    mma_tf32(oc[im][in_][0], oc[im][in_][1], oc[im][in_][2], oc[im][in_][3],
                             af[im][0], af[im][1], af[im][2], af[im][3],
                             bf[in_][0], bf[in_][1]);
        }
        __syncthreads();
    }

    // epilogue
    #pragma unroll
    for (int im = 0; im < 2; im++) {
        int r0r = warp_m + (im << 4) + g;
        float inv0 = 1.f / sL[r0r];
        float inv8 = 1.f / sL[r0r + 8];
        int R0 = bs0 + q0 + r0r;
        int R8 = R0 + 8;
        #pragma unroll
        for (int in_ = 0; in_ < 4; in_++) {
            int col = warp_nv + (in_ << 3) + tg*2;
#if T5_OK
            int Ccol = h * 128 + col;
            int chunk = Ccol >> 6, cin = Ccol & 63;
            {
                int tile = R0 >> 7, rin = R0 & 127;
                uint32_t sw = swz((uint32_t)(rin*128 + cin*2));
                size_t idx = ((size_t)(tile*32 + chunk) << 13) + (sw >> 1);
                float v0 = oc[im][in_][0]*inv0, v1 = oc[im][in_][1]*inv0;
                __nv_bfloat16 h0 = __float2bfloat16(v0), h1 = __float2bfloat16(v1);
                __nv_bfloat16 l0 = __float2bfloat16(v0 - __bfloat162float(h0));
                __nv_bfloat16 l1 = __float2bfloat16(v1 - __bfloat162float(h1));
                *(__nv_bfloat162*)&OHh[idx] = __halves2bfloat162(h0, h1);
                *(__nv_bfloat162*)&OHl[idx] = __halves2bfloat162(l0, l1);
            }
            {
                int tile = R8 >> 7, rin = R8 & 127;
                uint32_t sw = swz((uint32_t)(rin*128 + cin*2));
                size_t idx = ((size_t)(tile*32 + chunk) << 13) + (sw >> 1);
                float v2 = oc[im][in_][2]*inv8, v3 = oc[im][in_][3]*inv8;
                __nv_bfloat16 h2 = __float2bfloat16(v2), h3 = __float2bfloat16(v3);
                __nv_bfloat16 l2 = __float2bfloat16(v2 - __bfloat162float(h2));
                __nv_bfloat16 l3 = __float2bfloat16(v3 - __bfloat162float(h3));
                *(__nv_bfloat162*)&OHh[idx] = __halves2bfloat162(h2, h3);
                *(__nv_bfloat162*)&OHl[idx] = __halves2bfloat162(l2, l3);
            }
#else
            float* p0 = &OH[(size_t)R0 * (HH*VDIM) + h*VDIM + col];
            float* p8 = &OH[(size_t)R8 * (HH*VDIM) + h*VDIM + col];
            *(float2*)p0 = make_float2(tfr(oc[im][in_][0]*inv0), tfr(oc[im][in_][1]*inv0));
            *(float2*)p8 = make_float2(tfr(oc[im][in_][2]*inv8), tfr(oc[im][in_][3]*inv8));
#endif
        }
    }
}

// ---------------- launch ----------------
extern "C" void kernel_launch(void* const* d_in, const int* in_sizes, int n_in,
                              void* d_out, int out_size)
{
    const float* x      = (const float*)d_in[0];
    const float* wq     = (const float*)d_in[1];
    const float* wkv_a  = (const float*)d_in[2];
    const float* kvw    = (const float*)d_in[3];
    const float* wkv_b  = (const float*)d_in[4];
    const float* wo     = (const float*)d_in[5];
    const float* cosp   = (const float*)d_in[6];
    const float* sinp   = (const float*)d_in[7];
    float* out = (float*)d_out;

    float *Q, *KV, *CKV, *KPE, *KN, *V, *OH;
    float *Xr, *WQr, *WAr, *WBr, *WOr;
    __nv_bfloat16 *Xh, *Xl, *WQh, *WQl, *WAh, *WAl, *WBkh, *WBkl, *WBvh, *WBvl, *WOh, *WOl;
    __nv_bfloat16 *CKVh, *CKVl, *OHh, *OHl;
    cudaGetSymbolAddress((void**)&Q,    g_Q);
    cudaGetSymbolAddress((void**)&KV,   g_KV);
    cudaGetSymbolAddress((void**)&CKV,  g_CKV);
    cudaGetSymbolAddress((void**)&KPE,  g_KPE);
    cudaGetSymbolAddress((void**)&KN,   g_KN);
    cudaGetSymbolAddress((void**)&V,    g_V);
    cudaGetSymbolAddress((void**)&OH,   g_OH);
    cudaGetSymbolAddress((void**)&Xr,   g_Xr);
    cudaGetSymbolAddress((void**)&WQr,  g_WQr);
    cudaGetSymbolAddress((void**)&WAr,  g_WAr);
    cudaGetSymbolAddress((void**)&WBr,  g_WBr);
    cudaGetSymbolAddress((void**)&WOr,  g_WOr);
    cudaGetSymbolAddress((void**)&Xh,   g_Xh);   cudaGetSymbolAddress((void**)&Xl,   g_Xl);
    cudaGetSymbolAddress((void**)&WQh,  g_WQh);  cudaGetSymbolAddress((void**)&WQl,  g_WQl);
    cudaGetSymbolAddress((void**)&WAh,  g_WAh);  cudaGetSymbolAddress((void**)&WAl,  g_WAl);
    cudaGetSymbolAddress((void**)&WBkh, g_WBkh); cudaGetSymbolAddress((void**)&WBkl, g_WBkl);
    cudaGetSymbolAddress((void**)&WBvh, g_WBvh); cudaGetSymbolAddress((void**)&WBvl, g_WBvl);
    cudaGetSymbolAddress((void**)&WOh,  g_WOh);  cudaGetSymbolAddress((void**)&WOl,  g_WOl);
    cudaGetSymbolAddress((void**)&CKVh, g_CKVh); cudaGetSymbolAddress((void**)&CKVl, g_CKVl);
    cudaGetSymbolAddress((void**)&OHh,  g_OHh);  cudaGetSymbolAddress((void**)&OHl,  g_OHl);

    const int ASMEM = (64*SQS*2 + 128*SVS + 64*SPS + 3*64) * 4;
    cudaFuncSetAttribute(attn_kernel, cudaFuncAttributeMaxDynamicSharedMemorySize, ASMEM);
    cudaFuncSetAttribute(gemm_t5, cudaFuncAttributeMaxDynamicSharedMemorySize, GEMM_SMEM);

    const int BIGGRP = 1 << 30;

    // 0a. fallback preprocessing (no-op when tcgen05 active)
    {
        int n;
        n = BS*DIM/4;               round_tf32_kernel<<<(n+255)/256, 256>>>((const float4*)x,     (float4*)Xr,  n);
        n = (HH*QK)*DIM/4;          round_tf32_kernel<<<(n+255)/256, 256>>>((const float4*)wq,    (float4*)WQr, n);
        n = (KVR+ROPE)*DIM/4;       round_tf32_kernel<<<(n+255)/256, 256>>>((const float4*)wkv_a, (float4*)WAr, n);
        n = (HH*(NOPE+VDIM))*KVR/4; round_tf32_kernel<<<(n+255)/256, 256>>>((const float4*)wkv_b, (float4*)WBr, n);
        n = DIM*(HH*VDIM)/4;        round_tf32_kernel<<<(n+255)/256, 256>>>((const float4*)wo,    (float4*)WOr, n);
    }
    // 0b. tcgen05 preprocessing (no-op when fallback active)
    {
        size_t n;
        n = (size_t)BS*DIM;     split_A_kernel<<<(int)((n+255)/256), 256>>>(x, Xh, Xl, DIM, 32);
        n = (size_t)12*256*DIM; split_B_kernel<<<(int)((n+255)/256), 256>>>(wq, WQh, WQl, HH*QK, DIM, BIGGRP, 0, 0, n);
        n = (size_t)3*256*DIM;  split_B_kernel<<<(int)((n+255)/256), 256>>>(wkv_a, WAh, WAl, KVR+ROPE, DIM, BIGGRP, 0, 0, n);
        n = (size_t)8*256*KVR;  split_B_kernel<<<(int)((n+255)/256), 256>>>(wkv_b, WBkh, WBkl, HH*NOPE, KVR, 128, 256, 0, n);
        n = (size_t)8*256*KVR;  split_B_kernel<<<(int)((n+255)/256), 256>>>(wkv_b, WBvh, WBvl, HH*VDIM, KVR, 128, 256, 128, n);
        n = (size_t)8*256*DIM;  split_B_kernel<<<(int)((n+255)/256), 256>>>(wo, WOh, WOl, DIM, DIM, BIGGRP, 0, 0, n);
    }

    // 1. Q = X @ Wq^T
    gemm_tf32<<<dim3(24, 32), 256>>>(Xr, WQr, Q, BS, HH*QK, DIM, BIGGRP, 0, 0);
    gemm_t5<<<dim3(12, 32), 128, GEMM_SMEM>>>(Xh, Xl, WQh, WQl, Q, HH*QK, 32);
    // 2. rope q_pe
    rope_q_kernel<<<(BS*HH*32 + 255)/256, 256>>>(Q, cosp, sinp);
    // 3. KV = X @ Wkv_a^T
    gemm_tf32<<<dim3(5, 32), 256>>>(Xr, WAr, KV, BS, KVR+ROPE, DIM, BIGGRP, 0, 0);
    gemm_t5<<<dim3(3, 32), 128, GEMM_SMEM>>>(Xh, Xl, WAh, WAl, KV, KVR+ROPE, 32);
    // 4. rmsnorm + rope(k_pe)
    kv_post_kernel<<<BS, 128>>>(KV, kvw, cosp, sinp, CKV, CKVh, CKVl, KPE);
    // 5. k_nope
    gemm_tf32<<<dim3(16, 32), 256>>>(CKV, WBr, KN, BS, HH*NOPE, KVR, 128, 256, 0);
    gemm_t5<<<dim3(8, 32), 128, GEMM_SMEM>>>(CKVh, CKVl, WBkh, WBkl, KN, HH*NOPE, 8);
    // 6. v
    gemm_tf32<<<dim3(16, 32), 256>>>(CKV, WBr, V, BS, HH*VDIM, KVR, 128, 256, 128);
    gemm_t5<<<dim3(8, 32), 128, GEMM_SMEM>>>(CKVh, CKVl, WBvh, WBvl, V, HH*VDIM, 8);
    // 7. attention
    attn_kernel<<<dim3(SS/64, HH, BB), 256, ASMEM>>>(Q, KN, KPE, V, OH, OHh, OHl);
    // 8. out = OH @ wo^T
    gemm_tf32<<<dim3(16, 32), 256>>>(OH, WOr, out, BS, DIM, HH*VDIM, BIGGRP, 0, 0);
    gemm_t5<<<dim3(8, 32), 128, GEMM_SMEM>>>(OHh, OHl, WOh, WOl, out, DIM, 32);
}

// round 9
// speedup vs baseline: 4.8255x; 1.0061x over previous
#include <cuda_runtime.h>
#include <cuda_bf16.h>
#include <math.h>
#include <stdint.h>

// Arch-specific feature gate: tcgen05 only exists in the sm_103a-specific pass.
#if defined(__CUDA_ARCH__) && (defined(__CUDA_ARCH_FEAT_SM103_ALL) || (defined(__CUDA_ARCH_SPECIFIC__) && (__CUDA_ARCH_SPECIFIC__ == 1030)))
#define T5_OK 1
#else
#define T5_OK 0
#endif

// Problem constants
#define BB 2
#define SS 2048
#define DIM 2048
#define HH 16
#define KVR 512
#define NOPE 128
#define ROPE 64
#define VDIM 128
#define QK 192
#define BS (BB*SS)           // 4096
#define SCALE_C 0.07216878364870322f   // 192^-0.5
#define NEG_BIG -1e30f

// ---------------- fp32 scratch ----------------
__device__ float g_Q  [(size_t)BS * (HH*QK)];
__device__ float g_KV [(size_t)BS * (KVR+ROPE)];
__device__ float g_CKV[(size_t)BS * KVR];          // fallback path
__device__ float g_KPE[(size_t)BS * ROPE];
__device__ float g_KN [(size_t)BS * (HH*NOPE)];
__device__ float g_V  [(size_t)BS * (HH*VDIM)];
__device__ float g_OH [(size_t)BS * (HH*VDIM)];    // fallback path
// fallback tf32-rounded copies
__device__ float g_Xr [(size_t)BS * DIM];
__device__ float g_WQr[(size_t)(HH*QK) * DIM];
__device__ float g_WAr[(size_t)(KVR+ROPE) * DIM];
__device__ float g_WBr[(size_t)(HH*(NOPE+VDIM)) * KVR];
__device__ float g_WOr[(size_t)DIM * (HH*VDIM)];

// ---------------- bf16 split panel scratch (tcgen05 path) ----------------
#define APAN 8192
#define BPAN 16384
__device__ __align__(1024) __nv_bfloat16 g_Xh [(size_t)32*32*APAN],  g_Xl [(size_t)32*32*APAN];
__device__ __align__(1024) __nv_bfloat16 g_WQh[(size_t)12*32*BPAN],  g_WQl[(size_t)12*32*BPAN];
__device__ __align__(1024) __nv_bfloat16 g_WAh[(size_t)3*32*BPAN],   g_WAl[(size_t)3*32*BPAN];
__device__ __align__(1024) __nv_bfloat16 g_WBkh[(size_t)8*8*BPAN],   g_WBkl[(size_t)8*8*BPAN];
__device__ __align__(1024) __nv_bfloat16 g_WBvh[(size_t)8*8*BPAN],   g_WBvl[(size_t)8*8*BPAN];
__device__ __align__(1024) __nv_bfloat16 g_WOh[(size_t)8*32*BPAN],   g_WOl[(size_t)8*32*BPAN];
__device__ __align__(1024) __nv_bfloat16 g_CKVh[(size_t)32*8*APAN],  g_CKVl[(size_t)32*8*APAN];
__device__ __align__(1024) __nv_bfloat16 g_OHh[(size_t)32*32*APAN],  g_OHl[(size_t)32*32*APAN];

// ---------------- helpers ----------------
__device__ __forceinline__ uint32_t f2tf32(float x) {
    uint32_t r; asm("cvt.rna.tf32.f32 %0, %1;" : "=r"(r) : "f"(x)); return r;
}
__device__ __forceinline__ float tfr(float x) { return __uint_as_float(f2tf32(x)); }

__device__ __forceinline__ void mma_tf32(float& c0, float& c1, float& c2, float& c3,
                                         uint32_t a0, uint32_t a1, uint32_t a2, uint32_t a3,
                                         uint32_t b0, uint32_t b1)
{
    asm volatile(
        "mma.sync.aligned.m16n8k8.row.col.f32.tf32.tf32.f32 "
        "{%0,%1,%2,%3}, {%4,%5,%6,%7}, {%8,%9}, {%0,%1,%2,%3};\n"
        : "+f"(c0), "+f"(c1), "+f"(c2), "+f"(c3)
        : "r"(a0), "r"(a1), "r"(a2), "r"(a3), "r"(b0), "r"(b1));
}

__device__ __forceinline__ void cp_async16(uint32_t saddr, const void* gptr, int src_bytes) {
    asm volatile("cp.async.cg.shared.global [%0], [%1], 16, %2;\n"
                 :: "r"(saddr), "l"(gptr), "r"(src_bytes));
}
__device__ __forceinline__ void cp_commit() { asm volatile("cp.async.commit_group;\n"); }
template<int N> __device__ __forceinline__ void cp_wait() {
    asm volatile("cp.async.wait_group %0;\n" :: "n"(N));
}
__device__ __forceinline__ uint32_t swz(uint32_t off) { return off ^ ((off >> 3) & 0x70); }

#if T5_OK
__device__ __forceinline__ uint32_t smem_u32(const void* p) {
    uint32_t a;
    asm("{ .reg .u64 t; cvta.to.shared.u64 t, %1; cvt.u32.u64 %0, t; }" : "=r"(a) : "l"(p));
    return a;
}
__device__ __forceinline__ uint32_t elect_one() {
    uint32_t p;
    asm volatile("{\n\t.reg .pred p;\n\telect.sync _|p, 0xFFFFFFFF;\n\tselp.b32 %0, 1, 0, p;\n\t}" : "=r"(p));
    return p;
}
__device__ __forceinline__ void mbar_init(uint32_t a, uint32_t n) {
    asm volatile("mbarrier.init.shared.b64 [%0], %1;" :: "r"(a), "r"(n) : "memory");
}
__device__ __forceinline__ void mbar_inval(uint32_t a) {
    asm volatile("mbarrier.inval.shared.b64 [%0];" :: "r"(a) : "memory");
}
__device__ __forceinline__ void mbar_expect_tx(uint32_t a, uint32_t bytes) {
    asm volatile("mbarrier.arrive.expect_tx.shared.b64 _, [%0], %1;" :: "r"(a), "r"(bytes) : "memory");
}
__device__ __forceinline__ void mbar_wait(uint32_t a, uint32_t parity) {
    asm volatile(
        "{\n\t.reg .pred P;\n\t"
        "W_%=:\n\t"
        "mbarrier.try_wait.parity.acquire.cta.shared::cta.b64 P, [%0], %1, 0x989680;\n\t"
        "@P bra.uni D_%=;\n\t"
        "bra.uni W_%=;\n\t"
        "D_%=:\n\t}"
        :: "r"(a), "r"(parity) : "memory");
}
__device__ __forceinline__ void bulk_g2s(uint32_t dst, const void* src, uint32_t bytes, uint32_t mbar) {
    asm volatile(
        "cp.async.bulk.shared::cta.global.mbarrier::complete_tx::bytes [%0], [%1], %2, [%3];"
        :: "r"(dst), "l"(src), "r"(bytes), "r"(mbar) : "memory");
}
__device__ __forceinline__ void t5_alloc(uint32_t smem_res, uint32_t ncols) {
    asm volatile("tcgen05.alloc.cta_group::1.sync.aligned.shared::cta.b32 [%0], %1;"
                 :: "r"(smem_res), "r"(ncols) : "memory");
}
__device__ __forceinline__ void t5_dealloc(uint32_t tmem, uint32_t ncols) {
    asm volatile("tcgen05.dealloc.cta_group::1.sync.aligned.b32 %0, %1;" :: "r"(tmem), "r"(ncols));
}
__device__ __forceinline__ void t5_commit(uint32_t mbar) {
    asm volatile("tcgen05.commit.cta_group::1.mbarrier::arrive::one.shared::cluster.b64 [%0];"
                 :: "r"(mbar) : "memory");
}
__device__ __forceinline__ void t5_fence_after() {
    asm volatile("tcgen05.fence::after_thread_sync;" ::: "memory");
}
__device__ __forceinline__ void t5_wait_ld() {
    asm volatile("tcgen05.wait::ld.sync.aligned;" ::: "memory");
}
__device__ __forceinline__ void t5_mma_f16_ss(uint32_t d, uint64_t ad, uint64_t bd,
                                              uint32_t idesc, uint32_t en) {
    asm volatile(
        "{\n\t.reg .pred p;\n\t"
        "setp.ne.u32 p, %4, 0;\n\t"
        "tcgen05.mma.cta_group::1.kind::f16 [%0], %1, %2, %3, {%5,%5,%5,%5}, p;\n\t}"
        :: "r"(d), "l"(ad), "l"(bd), "r"(idesc), "r"(en), "r"(0u) : "memory");
}
static __device__ __forceinline__ uint64_t mk_desc(uint32_t addr) {
    const uint64_t base = (uint64_t(2) << 61) | (uint64_t(1) << 46)
                        | (uint64_t(64) << 32) | (uint64_t(1) << 16);
    return base | ((uint64_t)(addr >> 4) & 0x3FFF);
}
#define T5_IDESC ((1u<<4)|(1u<<7)|(1u<<10)|((256u/8u)<<17)|((128u/16u)<<24))
#endif  // T5_OK

// ---------------- preprocessing kernels ----------------
__global__ void round_tf32_kernel(const float4* __restrict__ src, float4* __restrict__ dst, int n4)
{
#if !T5_OK
    int i = blockIdx.x * blockDim.x + threadIdx.x;
    if (i >= n4) return;
    float4 v = src[i];
    v.x = tfr(v.x); v.y = tfr(v.y); v.z = tfr(v.z); v.w = tfr(v.w);
    dst[i] = v;
#endif
}

__global__ void split_A_kernel(const float* __restrict__ src,
                               __nv_bfloat16* __restrict__ dh, __nv_bfloat16* __restrict__ dl,
                               int K, int nchunks)
{
#if T5_OK
    size_t i = (size_t)blockIdx.x * 256 + threadIdx.x;
    if (i >= (size_t)BS * K) return;
    int row = (int)(i / K), k = (int)(i % K);
    float v = src[i];
    int tile = row >> 7, rin = row & 127, chunk = k >> 6, cin = k & 63;
    uint32_t sw = swz((uint32_t)(rin * 128 + cin * 2));
    size_t idx = ((size_t)(tile * nchunks + chunk) << 13) + (sw >> 1);
    __nv_bfloat16 h = __float2bfloat16(v);
    dh[idx] = h;
    dl[idx] = __float2bfloat16(v - __bfloat162float(h));
#endif
}

__global__ void split_B_kernel(const float* __restrict__ src,
                               __nv_bfloat16* __restrict__ dh, __nv_bfloat16* __restrict__ dl,
                               int Nrows, int K, int group, int gstride, int gbase, size_t total)
{
#if T5_OK
    size_t i = (size_t)blockIdx.x * 256 + threadIdx.x;
    if (i >= total) return;
    int n = (int)(i / K), k = (int)(i % K);
    float v = 0.f;
    if (n < Nrows) {
        int br = gbase + (n / group) * gstride + (n % group);
        v = src[(size_t)br * K + k];
    }
    int tile = n >> 8, rin = n & 255, chunk = k >> 6, cin = k & 63;
    int nchunks = K >> 6;
    uint32_t sw = swz((uint32_t)(rin * 128 + cin * 2));
    size_t idx = ((size_t)(tile * nchunks + chunk) << 14) + (sw >> 1);
    __nv_bfloat16 h = __float2bfloat16(v);
    dh[idx] = h;
    dl[idx] = __float2bfloat16(v - __bfloat162float(h));
#endif
}

// ---------------- fallback tf32 GEMM (R3, proven) ----------------
#define NST 3
__global__ __launch_bounds__(256)
void gemm_tf32(const float* __restrict__ A, const float* __restrict__ B,
               float* __restrict__ C, int M, int N, int K,
               int group, int gstride, int gbase)
{
#if !T5_OK
    __shared__ uint32_t As[NST][128][20];
    __shared__ uint32_t Bs[NST][128][20];

    const int tid  = threadIdx.x;
    const int lane = tid & 31;
    const int warp = tid >> 5;
    const int row0 = blockIdx.y * 128;
    const int col0 = blockIdx.x * 128;

    const int warp_m = (warp & 1) * 64;
    const int warp_n = (warp >> 1) * 32;
    const int g  = lane >> 2;
    const int tg = lane & 3;

    int r0q = (tid) >> 2,        kq0 = (tid & 3) << 2;
    int r1q = (tid + 256) >> 2,  kq1 = ((tid + 256) & 3) << 2;

    const float* A0 = A + (size_t)(row0 + r0q) * K + kq0;
    const float* A1 = A + (size_t)(row0 + r1q) * K + kq1;

    int bn0 = col0 + r0q, bn1 = col0 + r1q;
    int bok0 = (bn0 < N) ? 16 : 0;
    int bok1 = (bn1 < N) ? 16 : 0;
    int br0 = bok0 ? (gbase + (bn0 / group) * gstride + (bn0 % group)) : 0;
    int br1 = bok1 ? (gbase + (bn1 / group) * gstride + (bn1 % group)) : 0;
    const float* B0 = B + (size_t)br0 * K + kq0;
    const float* B1 = B + (size_t)br1 * K + kq1;

    uint32_t sa0[NST], sa1[NST], sb0[NST], sb1[NST];
    #pragma unroll
    for (int s = 0; s < NST; s++) {
        sa0[s] = (uint32_t)__cvta_generic_to_shared(&As[s][r0q][kq0]);
        sa1[s] = (uint32_t)__cvta_generic_to_shared(&As[s][r1q][kq1]);
        sb0[s] = (uint32_t)__cvta_generic_to_shared(&Bs[s][r0q][kq0]);
        sb1[s] = (uint32_t)__cvta_generic_to_shared(&Bs[s][r1q][kq1]);
    }

    float acc[4][4][4];
    #pragma unroll
    for (int i = 0; i < 4; i++)
        #pragma unroll
        for (int j = 0; j < 4; j++)
            #pragma unroll
            for (int r = 0; r < 4; r++) acc[i][j][r] = 0.f;

    const int nk = K >> 4;

    #pragma unroll
    for (int s = 0; s < NST - 1; s++) {
        int ko = s << 4;
        cp_async16(sa0[s], A0 + ko, 16);
        cp_async16(sa1[s], A1 + ko, 16);
        cp_async16(sb0[s], B0 + ko, bok0);
        cp_async16(sb1[s], B1 + ko, bok1);
        cp_commit();
    }

    for (int kt = 0; kt < nk; kt++) {
        const int st = kt % NST;
        cp_wait<NST - 2>();
        __syncthreads();

        #pragma unroll
        for (int kk = 0; kk < 16; kk += 8) {
            uint32_t af[4][4], bf[4][2];
            #pragma unroll
            for (int im = 0; im < 4; im++) {
                int mb = warp_m + (im << 4);
                af[im][0] = As[st][mb + g    ][kk + tg];
                af[im][1] = As[st][mb + g + 8][kk + tg];
                af[im][2] = As[st][mb + g    ][kk + tg + 4];
                af[im][3] = As[st][mb + g + 8][kk + tg + 4];
            }
            #pragma unroll
            for (int in_ = 0; in_ < 4; in_++) {
                int nb = warp_n + (in_ << 3);
                bf[in_][0] = Bs[st][nb + g][kk + tg];
                bf[in_][1] = Bs[st][nb + g][kk + tg + 4];
            }
            #pragma unroll
            for (int im = 0; im < 4; im++)
                #pragma unroll
                for (int in_ = 0; in_ < 4; in_++)
                    mma_tf32(acc[im][in_][0], acc[im][in_][1], acc[im][in_][2], acc[im][in_][3],
                             af[im][0], af[im][1], af[im][2], af[im][3],
                             bf[in_][0], bf[in_][1]);
        }
        __syncthreads();

        int knext = kt + NST - 1;
        if (knext < nk) {
            int sn = knext % NST;
            int ko = knext << 4;
            cp_async16(sa0[sn], A0 + ko, 16);
            cp_async16(sa1[sn], A1 + ko, 16);
            cp_async16(sb0[sn], B0 + ko, bok0);
            cp_async16(sb1[sn], B1 + ko, bok1);
        }
        cp_commit();
    }

    #pragma unroll
    for (int im = 0; im < 4; im++) {
        #pragma unroll
        for (int in_ = 0; in_ < 4; in_++) {
            int row = row0 + warp_m + (im << 4) + g;
            int col = col0 + warp_n + (in_ << 3) + tg * 2;
            if (col < N) {
                *(float2*)(C + (size_t)row * N + col) =
                    make_float2(acc[im][in_][0], acc[im][in_][1]);
                *(float2*)(C + (size_t)(row + 8) * N + col) =
                    make_float2(acc[im][in_][2], acc[im][in_][3]);
            }
        }
    }
#endif
}

// ---------------- tcgen05 bf16x3 GEMM ----------------
#define SM_TMPTR 0
#define SM_FULL0 16
#define SM_FREE0 32
#define SM_DONE  48
#define SM_STG0  1024
#define STG_BYTES 98304
#define OFF_AH 0
#define OFF_AL 16384
#define OFF_BH 32768
#define OFF_BL 65536
#define GEMM_SMEM (1024 + 2*STG_BYTES)

__global__ __launch_bounds__(128, 1)
void gemm_t5(const __nv_bfloat16* __restrict__ Ah, const __nv_bfloat16* __restrict__ Al,
             const __nv_bfloat16* __restrict__ Bh, const __nv_bfloat16* __restrict__ Bl,
             float* __restrict__ C, int N, int nchunks)
{
#if T5_OK
    extern __shared__ __align__(1024) char smraw[];
    const uint32_t smb = smem_u32(smraw);
    const int tid  = threadIdx.x;
    const int warp = tid >> 5;
    const int lane = tid & 31;
    const int tile_n = blockIdx.x;
    const int tile_m = blockIdx.y;

    if (tid == 0) {
        mbar_init(smb + SM_FULL0 + 0, 1);
        mbar_init(smb + SM_FULL0 + 8, 1);
        mbar_init(smb + SM_FREE0 + 0, 1);
        mbar_init(smb + SM_FREE0 + 8, 1);
        mbar_init(smb + SM_DONE, 1);
    }
    if (warp == 1) t5_alloc(smb + SM_TMPTR, 512);
    __syncthreads();
    uint32_t tmem;
    asm volatile("ld.shared.b32 %0, [%1];" : "=r"(tmem) : "r"(smb + SM_TMPTR));

    if (warp == 0) {
        if (elect_one()) {
            uint32_t pph = 1;
            const size_t abase = (size_t)tile_m * nchunks;
            const size_t bbase = (size_t)tile_n * nchunks;
            for (int c = 0; c < nchunks; c++) {
                int s = c & 1;
                uint32_t stg = smb + SM_STG0 + s * STG_BYTES;
                mbar_wait(smb + SM_FREE0 + s * 8, pph);
                mbar_expect_tx(smb + SM_FULL0 + s * 8, STG_BYTES);
                bulk_g2s(stg + OFF_AH, Ah + (abase + c) * APAN, 16384, smb + SM_FULL0 + s * 8);
                bulk_g2s(stg + OFF_AL, Al + (abase + c) * APAN, 16384, smb + SM_FULL0 + s * 8);
                bulk_g2s(stg + OFF_BH, Bh + (bbase + c) * BPAN, 32768, smb + SM_FULL0 + s * 8);
                bulk_g2s(stg + OFF_BL, Bl + (bbase + c) * BPAN, 32768, smb + SM_FULL0 + s * 8);
                if (s == 1) pph ^= 1;
            }
        }
    }
    if (warp == 1) {
        if (elect_one()) {
            uint32_t cph = 0;
            for (int c = 0; c < nchunks; c++) {
                int s = c & 1;
                uint32_t stg = smb + SM_STG0 + s * STG_BYTES;
                mbar_wait(smb + SM_FULL0 + s * 8, cph);
                uint64_t ahd = mk_desc(stg + OFF_AH);
                uint64_t ald = mk_desc(stg + OFF_AL);
                uint64_t bhd = mk_desc(stg + OFF_BH);
                uint64_t bld = mk_desc(stg + OFF_BL);
                uint64_t ads[3] = {ahd, ahd, ald};
                uint64_t bds[3] = {bhd, bld, bhd};
                #pragma unroll
                for (int p = 0; p < 3; p++) {
                    #pragma unroll
                    for (int k = 0; k < 4; k++) {
                        uint32_t en = (c | p | k) ? 1u : 0u;
                        t5_mma_f16_ss(tmem, ads[p] + k * 2, bds[p] + k * 2, T5_IDESC, en);
                    }
                }
                t5_commit(smb + SM_FREE0 + s * 8);
                if (c == nchunks - 1) t5_commit(smb + SM_DONE);
                if (s == 1) cph ^= 1;
            }
        }
    }

    mbar_wait(smb + SM_DONE, 0);
    t5_fence_after();

    const int gr = (tile_m << 7) + (warp << 5) + lane;
    #pragma unroll 1
    for (int cb = 0; cb < 8; cb++) {
        uint32_t d[32];
        asm volatile(
            "tcgen05.ld.sync.aligned.32x32b.x32.b32 "
            "{%0, %1, %2, %3, %4, %5, %6, %7, "
            " %8, %9, %10, %11, %12, %13, %14, %15, "
            " %16, %17, %18, %19, %20, %21, %22, %23, "
            " %24, %25, %26, %27, %28, %29, %30, %31}, [%32];"
            : "=r"(d[0]),  "=r"(d[1]),  "=r"(d[2]),  "=r"(d[3]),
              "=r"(d[4]),  "=r"(d[5]),  "=r"(d[6]),  "=r"(d[7]),
              "=r"(d[8]),  "=r"(d[9]),  "=r"(d[10]), "=r"(d[11]),
              "=r"(d[12]), "=r"(d[13]), "=r"(d[14]), "=r"(d[15]),
              "=r"(d[16]), "=r"(d[17]), "=r"(d[18]), "=r"(d[19]),
              "=r"(d[20]), "=r"(d[21]), "=r"(d[22]), "=r"(d[23]),
              "=r"(d[24]), "=r"(d[25]), "=r"(d[26]), "=r"(d[27]),
              "=r"(d[28]), "=r"(d[29]), "=r"(d[30]), "=r"(d[31])
            : "r"(tmem + cb * 32));
        t5_wait_ld();
        int gc0 = (tile_n << 8) + (cb << 5);
        float* cp = C + (size_t)gr * N + gc0;
        #pragma unroll
        for (int j = 0; j < 32; j += 4) {
            if (gc0 + j < N)
                *(float4*)(cp + j) = make_float4(__uint_as_float(d[j]),   __uint_as_float(d[j+1]),
                                                 __uint_as_float(d[j+2]), __uint_as_float(d[j+3]));
        }
    }

    __syncthreads();
    if (tid == 0) {
        mbar_inval(smb + SM_FULL0 + 0); mbar_inval(smb + SM_FULL0 + 8);
        mbar_inval(smb + SM_FREE0 + 0); mbar_inval(smb + SM_FREE0 + 8);
        mbar_inval(smb + SM_DONE);
    }
    if (warp == 1) t5_dealloc(tmem, 512);
#endif
}

// ---------------- RoPE on q_pe part of Q (in place) ----------------
__global__ void rope_q_kernel(float* __restrict__ Q,
                              const float* __restrict__ COS,
                              const float* __restrict__ SIN)
{
    int idx = blockIdx.x * blockDim.x + threadIdx.x;
    if (idx >= BS * HH * 32) return;
    int i = idx & 31;
    int h = (idx >> 5) & 15;
    int m = idx >> 9;
    int s = m & (SS - 1);
    size_t base = (size_t)m * (HH*QK) + h * QK + NOPE + 2*i;
    float xe = Q[base], xo = Q[base + 1];
    float c  = COS[s*32 + i], sn = SIN[s*32 + i];
    Q[base]     = xe*c - xo*sn;
    Q[base + 1] = xe*sn + xo*c;
}

// ---------------- KV post ----------------
__global__ void kv_post_kernel(const float* __restrict__ KV,
                               const float* __restrict__ W,
                               const float* __restrict__ COS,
                               const float* __restrict__ SIN,
                               float* __restrict__ CKV,
                               __nv_bfloat16* __restrict__ CKVh,
                               __nv_bfloat16* __restrict__ CKVl,
                               float* __restrict__ KPE)
{
    __shared__ float red[4];
    __shared__ float rs_s;
    const int m = blockIdx.x;
    const int tid = threadIdx.x; // 128 threads
    const float* row = KV + (size_t)m * (KVR+ROPE);

    float ss = 0.f;
    for (int c = tid; c < KVR; c += 128) { float v = row[c]; ss += v * v; }
    #pragma unroll
    for (int o = 16; o; o >>= 1) ss += __shfl_xor_sync(0xffffffffu, ss, o);
    if ((tid & 31) == 0) red[tid >> 5] = ss;
    __syncthreads();
    if (tid == 0) {
        float t = red[0] + red[1] + red[2] + red[3];
        rs_s = rsqrtf(t / (float)KVR + 1e-6f);
    }
    __syncthreads();
    float rs = rs_s;
#if T5_OK
    const int tile = m >> 7, rin = m & 127;
    for (int c = tid; c < KVR; c += 128) {
        float v = row[c] * rs * W[c];
        int chunk = c >> 6, cin = c & 63;
        uint32_t sw = swz((uint32_t)(rin * 128 + cin * 2));
        size_t idx = ((size_t)(tile * 8 + chunk) << 13) + (sw >> 1);
        __nv_bfloat16 h = __float2bfloat16(v);
        CKVh[idx] = h;
        CKVl[idx] = __float2bfloat16(v - __bfloat162float(h));
    }
#else
    for (int c = tid; c < KVR; c += 128)
        CKV[(size_t)m * KVR + c] = tfr(row[c] * rs * W[c]);
#endif

    if (tid < 32) {
        int i = tid;
        int s = m & (SS - 1);
        float xe = row[KVR + 2*i], xo = row[KVR + 2*i + 1];
        float c  = COS[s*32 + i], sn = SIN[s*32 + i];
        KPE[(size_t)m * ROPE + 2*i]     = xe*c - xo*sn;
        KPE[(size_t)m * ROPE + 2*i + 1] = xe*sn + xo*c;
    }
}

// ---------------- flash attention (tf32 mma) ----------------
#define SQS 196
#define SVS 69
#define SPS 68
__global__ __launch_bounds__(256, 1)
void attn_kernel(const float* __restrict__ Q,
                 const float* __restrict__ KN,
                 const float* __restrict__ KPE,
                 const float* __restrict__ V,
                 float* __restrict__ OH,
                 __nv_bfloat16* __restrict__ OHh,
                 __nv_bfloat16* __restrict__ OHl)
{
    extern __shared__ float smem[];
    float* sQ  = smem;
    float* sK  = sQ  + 64*SQS;
    float* sVt = sK  + 64*SQS;
    float* sP  = sVt + 128*SVS;
    float* sM  = sP  + 64*SPS;
    float* sL  = sM  + 64;
    float* sAl = sL  + 64;

    const int tid  = threadIdx.x;
    const int lane = tid & 31;
    const int warp = tid >> 5;
    const int g  = lane >> 2;
    const int tg = lane & 3;
    const int q0  = blockIdx.x * 64;
    const int h   = blockIdx.y;
    const int b   = blockIdx.z;
    const int bs0 = b * SS;

    const int warp_m  = (warp & 1) * 32;
    const int warp_ns = (warp >> 1) * 16;
    const int warp_nv = (warp >> 1) * 32;

    for (int i = tid; i < 64*48; i += 256) {
        int r = i / 48, qq = i % 48;
        float4 v = *(const float4*)(Q + (size_t)(bs0 + q0 + r) * (HH*QK) + h*QK + qq*4);
        float* d = &sQ[r*SQS + qq*4];
        d[0] = tfr(v.x); d[1] = tfr(v.y); d[2] = tfr(v.z); d[3] = tfr(v.w);
    }
    if (tid < 64) { sM[tid] = NEG_BIG; sL[tid] = 0.f; }

    float oc[2][4][4];
    #pragma unroll
    for (int i = 0; i < 2; i++)
        #pragma unroll
        for (int j = 0; j < 4; j++)
            #pragma unroll
            for (int r = 0; r < 4; r++) oc[i][j][r] = 0.f;

    __syncthreads();

    const int ntiles = q0/64 + 1;
    for (int tt = 0; tt < ntiles; tt++) {
        const int t0 = tt * 64;
        for (int i = tid; i < 64*48; i += 256) {
            int t = i / 48, qq = i % 48;
            float4 v;
            if (qq < 32) v = *(const float4*)(KN  + (size_t)(bs0 + t0 + t) * (HH*NOPE) + h*NOPE + qq*4);
            else         v = *(const float4*)(KPE + (size_t)(bs0 + t0 + t) * ROPE + (qq-32)*4);
            float* d = &sK[t*SQS + qq*4];
            d[0] = tfr(v.x); d[1] = tfr(v.y); d[2] = tfr(v.z); d[3] = tfr(v.w);
        }
        for (int i = tid; i < 64*32; i += 256) {
            int t = i >> 5, c4 = (i & 31) << 2;
            float4 v = *(const float4*)(V + (size_t)(bs0 + t0 + t) * (HH*VDIM) + h*VDIM + c4);
            sVt[(c4+0)*SVS + t] = tfr(v.x);
            sVt[(c4+1)*SVS + t] = tfr(v.y);
            sVt[(c4+2)*SVS + t] = tfr(v.z);
            sVt[(c4+3)*SVS + t] = tfr(v.w);
        }
        __syncthreads();

        float sc[2][2][4];
        #pragma unroll
        for (int i = 0; i < 2; i++)
            #pragma unroll
            for (int j = 0; j < 2; j++)
                #pragma unroll
                for (int r = 0; r < 4; r++) sc[i][j][r] = 0.f;

        #pragma unroll 4
        for (int k8 = 0; k8 < 192; k8 += 8) {
            uint32_t af[2][4], bf[2][2];
            #pragma unroll
            for (int im = 0; im < 2; im++) {
                int mb = warp_m + (im << 4);
                af[im][0] = __float_as_uint(sQ[(mb + g    )*SQS + k8 + tg]);
                af[im][1] = __float_as_uint(sQ[(mb + g + 8)*SQS + k8 + tg]);
                af[im][2] = __float_as_uint(sQ[(mb + g    )*SQS + k8 + tg + 4]);
                af[im][3] = __float_as_uint(sQ[(mb + g + 8)*SQS + k8 + tg + 4]);
            }
            #pragma unroll
            for (int in_ = 0; in_ < 2; in_++) {
                int nb = warp_ns + (in_ << 3);
                bf[in_][0] = __float_as_uint(sK[(nb + g)*SQS + k8 + tg]);
                bf[in_][1] = __float_as_uint(sK[(nb + g)*SQS + k8 + tg + 4]);
            }
            #pragma unroll
            for (int im = 0; im < 2; im++)
                #pragma unroll
                for (int in_ = 0; in_ < 2; in_++)
                    mma_tf32(sc[im][in_][0], sc[im][in_][1], sc[im][in_][2], sc[im][in_][3],
                             af[im][0], af[im][1], af[im][2], af[im][3],
                             bf[in_][0], bf[in_][1]);
        }

        const bool diag = (tt == ntiles - 1);
        #pragma unroll
        for (int im = 0; im < 2; im++) {
            int r0r = warp_m + (im << 4) + g;
            #pragma unroll
            for (int in_ = 0; in_ < 2; in_++) {
                int c0c = warp_ns + (in_ << 3) + tg*2;
                float v0 = sc[im][in_][0] * SCALE_C;
                float v1 = sc[im][in_][1] * SCALE_C;
                float v2 = sc[im][in_][2] * SCALE_C;
                float v3 = sc[im][in_][3] * SCALE_C;
                if (diag) {
                    if (c0c     > r0r    ) v0 = NEG_BIG;
                    if (c0c + 1 > r0r    ) v1 = NEG_BIG;
                    if (c0c     > r0r + 8) v2 = NEG_BIG;
                    if (c0c + 1 > r0r + 8) v3 = NEG_BIG;
                }
                sP[ r0r     *SPS + c0c    ] = v0;
                sP[ r0r     *SPS + c0c + 1] = v1;
                sP[(r0r + 8)*SPS + c0c    ] = v2;
                sP[(r0r + 8)*SPS + c0c + 1] = v3;
            }
        }
        __syncthreads();

        {
            int r   = tid >> 2;
            int seg = tid & 3;
            float* prow = &sP[r*SPS + seg*16];
            float mx = NEG_BIG;
            #pragma unroll
            for (int j = 0; j < 16; j++) mx = fmaxf(mx, prow[j]);
            #pragma unroll
            for (int o = 1; o < 4; o <<= 1) mx = fmaxf(mx, __shfl_xor_sync(0xffffffffu, mx, o));
            float mold = sM[r];
            float mnew = fmaxf(mold, mx);
            float alpha = __expf(mold - mnew);
            float lsum = 0.f;
            #pragma unroll
            for (int j = 0; j < 16; j++) {
                float e = __expf(prow[j] - mnew);
                prow[j] = tfr(e);
                lsum += e;
            }
            #pragma unroll
            for (int o = 1; o < 4; o <<= 1) lsum += __shfl_xor_sync(0xffffffffu, lsum, o);
            if (seg == 0) { sM[r] = mnew; sL[r] = sL[r]*alpha + lsum; sAl[r] = alpha; }
        }
        __syncthreads();

        #pragma unroll
        for (int im = 0; im < 2; im++) {
            float al0 = sAl[warp_m + (im << 4) + g];
            float al8 = sAl[warp_m + (im << 4) + g + 8];
            #pragma unroll
            for (int in_ = 0; in_ < 4; in_++) {
                oc[im][in_][0] *= al0; oc[im][in_][1] *= al0;
                oc[im][in_][2] *= al8; oc[im][in_][3] *= al8;
            }
        }
        #pragma unroll
        for (int k8 = 0; k8 < 64; k8 += 8) {
            uint32_t af[2][4], bf[4][2];
            #pragma unroll
            for (int im = 0; im < 2; im++) {
                int mb = warp_m + (im << 4);
                af[im][0] = __float_as_uint(sP[(mb + g    )*SPS + k8 + tg]);
                af[im][1] = __float_as_uint(sP[(mb + g + 8)*SPS + k8 + tg]);
                af[im][2] = __float_as_uint(sP[(mb + g    )*SPS + k8 + tg + 4]);
                af[im][3] = __float_as_uint(sP[(mb + g + 8)*SPS + k8 + tg + 4]);
            }
            #pragma unroll
            for (int in_ = 0; in_ < 4; in_++) {
                int nb = warp_nv + (in_ << 3);
                bf[in_][0] = __float_as_uint(sVt[(nb + g)*SVS + k8 + tg]);
                bf[in_][1] = __float_as_uint(sVt[(nb + g)*SVS + k8 + tg + 4]);
            }
            #pragma unroll
            for (int im = 0; im < 2; im++)
                #pragma unroll
                for (int in_ = 0; in_ < 4; in_++)
                    mma_tf32(oc[im][in_][0], oc[im][in_][1], oc[im][in_][2], oc[im][in_][3],
                             af[im][0], af[im][1], af[im][2], af[im][3],
                             bf[in_][0], bf[in_][1]);
        }
        __syncthreads();
    }

    // epilogue
    #pragma unroll
    for (int im = 0; im < 2; im++) {
        int r0r = warp_m + (im << 4) + g;
        float inv0 = 1.f / sL[r0r];
        float inv8 = 1.f / sL[r0r + 8];
        int R0 = bs0 + q0 + r0r;
        int R8 = R0 + 8;
        #pragma unroll
        for (int in_ = 0; in_ < 4; in_++) {
            int col = warp_nv + (in_ << 3) + tg*2;
#if T5_OK
            int Ccol = h * 128 + col;
            int chunk = Ccol >> 6, cin = Ccol & 63;
            {
                int tile = R0 >> 7, rin = R0 & 127;
                uint32_t sw = swz((uint32_t)(rin*128 + cin*2));
                size_t idx = ((size_t)(tile*32 + chunk) << 13) + (sw >> 1);
                float v0 = oc[im][in_][0]*inv0, v1 = oc[im][in_][1]*inv0;
                __nv_bfloat16 h0 = __float2bfloat16(v0), h1 = __float2bfloat16(v1);
                __nv_bfloat16 l0 = __float2bfloat16(v0 - __bfloat162float(h0));
                __nv_bfloat16 l1 = __float2bfloat16(v1 - __bfloat162float(h1));
                *(__nv_bfloat162*)&OHh[idx] = __halves2bfloat162(h0, h1);
                *(__nv_bfloat162*)&OHl[idx] = __halves2bfloat162(l0, l1);
            }
            {
                int tile = R8 >> 7, rin = R8 & 127;
                uint32_t sw = swz((uint32_t)(rin*128 + cin*2));
                size_t idx = ((size_t)(tile*32 + chunk) << 13) + (sw >> 1);
                float v2 = oc[im][in_][2]*inv8, v3 = oc[im][in_][3]*inv8;
                __nv_bfloat16 h2 = __float2bfloat16(v2), h3 = __float2bfloat16(v3);
                __nv_bfloat16 l2 = __float2bfloat16(v2 - __bfloat162float(h2));
                __nv_bfloat16 l3 = __float2bfloat16(v3 - __bfloat162float(h3));
                *(__nv_bfloat162*)&OHh[idx] = __halves2bfloat162(h2, h3);
                *(__nv_bfloat162*)&OHl[idx] = __halves2bfloat162(l2, l3);
            }
#else
            float* p0 = &OH[(size_t)R0 * (HH*VDIM) + h*VDIM + col];
            float* p8 = &OH[(size_t)R8 * (HH*VDIM) + h*VDIM + col];
            *(float2*)p0 = make_float2(tfr(oc[im][in_][0]*inv0), tfr(oc[im][in_][1]*inv0));
            *(float2*)p8 = make_float2(tfr(oc[im][in_][2]*inv8), tfr(oc[im][in_][3]*inv8));
#endif
        }
    }
}

// ---------------- launch ----------------
extern "C" void kernel_launch(void* const* d_in, const int* in_sizes, int n_in,
                              void* d_out, int out_size)
{
    const float* x      = (const float*)d_in[0];
    const float* wq     = (const float*)d_in[1];
    const float* wkv_a  = (const float*)d_in[2];
    const float* kvw    = (const float*)d_in[3];
    const float* wkv_b  = (const float*)d_in[4];
    const float* wo     = (const float*)d_in[5];
    const float* cosp   = (const float*)d_in[6];
    const float* sinp   = (const float*)d_in[7];
    float* out = (float*)d_out;

    float *Q, *KV, *CKV, *KPE, *KN, *V, *OH;
    float *Xr, *WQr, *WAr, *WBr, *WOr;
    __nv_bfloat16 *Xh, *Xl, *WQh, *WQl, *WAh, *WAl, *WBkh, *WBkl, *WBvh, *WBvl, *WOh, *WOl;
    __nv_bfloat16 *CKVh, *CKVl, *OHh, *OHl;
    cudaGetSymbolAddress((void**)&Q,    g_Q);
    cudaGetSymbolAddress((void**)&KV,   g_KV);
    cudaGetSymbolAddress((void**)&CKV,  g_CKV);
    cudaGetSymbolAddress((void**)&KPE,  g_KPE);
    cudaGetSymbolAddress((void**)&KN,   g_KN);
    cudaGetSymbolAddress((void**)&V,    g_V);
    cudaGetSymbolAddress((void**)&OH,   g_OH);
    cudaGetSymbolAddress((void**)&Xr,   g_Xr);
    cudaGetSymbolAddress((void**)&WQr,  g_WQr);
    cudaGetSymbolAddress((void**)&WAr,  g_WAr);
    cudaGetSymbolAddress((void**)&WBr,  g_WBr);
    cudaGetSymbolAddress((void**)&WOr,  g_WOr);
    cudaGetSymbolAddress((void**)&Xh,   g_Xh);   cudaGetSymbolAddress((void**)&Xl,   g_Xl);
    cudaGetSymbolAddress((void**)&WQh,  g_WQh);  cudaGetSymbolAddress((void**)&WQl,  g_WQl);
    cudaGetSymbolAddress((void**)&WAh,  g_WAh);  cudaGetSymbolAddress((void**)&WAl,  g_WAl);
    cudaGetSymbolAddress((void**)&WBkh, g_WBkh); cudaGetSymbolAddress((void**)&WBkl, g_WBkl);
    cudaGetSymbolAddress((void**)&WBvh, g_WBvh); cudaGetSymbolAddress((void**)&WBvl, g_WBvl);
    cudaGetSymbolAddress((void**)&WOh,  g_WOh);  cudaGetSymbolAddress((void**)&WOl,  g_WOl);
    cudaGetSymbolAddress((void**)&CKVh, g_CKVh); cudaGetSymbolAddress((void**)&CKVl, g_CKVl);
    cudaGetSymbolAddress((void**)&OHh,  g_OHh);  cudaGetSymbolAddress((void**)&OHl,  g_OHl);

    const int ASMEM = (64*SQS*2 + 128*SVS + 64*SPS + 3*64) * 4;
    cudaFuncSetAttribute(attn_kernel, cudaFuncAttributeMaxDynamicSharedMemorySize, ASMEM);
    cudaFuncSetAttribute(gemm_t5, cudaFuncAttributeMaxDynamicSharedMemorySize, GEMM_SMEM);

    const int BIGGRP = 1 << 30;

    // 0a. fallback preprocessing (no-op when tcgen05 active)
    {
        int n;
        n = BS*DIM/4;               round_tf32_kernel<<<(n+255)/256, 256>>>((const float4*)x,     (float4*)Xr,  n);
        n = (HH*QK)*DIM/4;          round_tf32_kernel<<<(n+255)/256, 256>>>((const float4*)wq,    (float4*)WQr, n);
        n = (KVR+ROPE)*DIM/4;       round_tf32_kernel<<<(n+255)/256, 256>>>((const float4*)wkv_a, (float4*)WAr, n);
        n = (HH*(NOPE+VDIM))*KVR/4; round_tf32_kernel<<<(n+255)/256, 256>>>((const float4*)wkv_b, (float4*)WBr, n);
        n = DIM*(HH*VDIM)/4;        round_tf32_kernel<<<(n+255)/256, 256>>>((const float4*)wo,    (float4*)WOr, n);
    }
    // 0b. tcgen05 preprocessing (no-op when fallback active)
    {
        size_t n;
        n = (size_t)BS*DIM;     split_A_kernel<<<(int)((n+255)/256), 256>>>(x, Xh, Xl, DIM, 32);
        n = (size_t)12*256*DIM; split_B_kernel<<<(int)((n+255)/256), 256>>>(wq, WQh, WQl, HH*QK, DIM, BIGGRP, 0, 0, n);
        n = (size_t)3*256*DIM;  split_B_kernel<<<(int)((n+255)/256), 256>>>(wkv_a, WAh, WAl, KVR+ROPE, DIM, BIGGRP, 0, 0, n);
        n = (size_t)8*256*KVR;  split_B_kernel<<<(int)((n+255)/256), 256>>>(wkv_b, WBkh, WBkl, HH*NOPE, KVR, 128, 256, 0, n);
        n = (size_t)8*256*KVR;  split_B_kernel<<<(int)((n+255)/256), 256>>>(wkv_b, WBvh, WBvl, HH*VDIM, KVR, 128, 256, 128, n);
        n = (size_t)8*256*DIM;  split_B_kernel<<<(int)((n+255)/256), 256>>>(wo, WOh, WOl, DIM, DIM, BIGGRP, 0, 0, n);
    }

    // 1. Q = X @ Wq^T
    gemm_tf32<<<dim3(24, 32), 256>>>(Xr, WQr, Q, BS, HH*QK, DIM, BIGGRP, 0, 0);
    gemm_t5<<<dim3(12, 32), 128, GEMM_SMEM>>>(Xh, Xl, WQh, WQl, Q, HH*QK, 32);
    // 2. rope q_pe
    rope_q_kernel<<<(BS*HH*32 + 255)/256, 256>>>(Q, cosp, sinp);
    // 3. KV = X @ Wkv_a^T
    gemm_tf32<<<dim3(5, 32), 256>>>(Xr, WAr, KV, BS, KVR+ROPE, DIM, BIGGRP, 0, 0);
    gemm_t5<<<dim3(3, 32), 128, GEMM_SMEM>>>(Xh, Xl, WAh, WAl, KV, KVR+ROPE, 32);
    // 4. rmsnorm + rope(k_pe)
    kv_post_kernel<<<BS, 128>>>(KV, kvw, cosp, sinp, CKV, CKVh, CKVl, KPE);
    // 5. k_nope
    gemm_tf32<<<dim3(16, 32), 256>>>(CKV, WBr, KN, BS, HH*NOPE, KVR, 128, 256, 0);
    gemm_t5<<<dim3(8, 32), 128, GEMM_SMEM>>>(CKVh, CKVl, WBkh, WBkl, KN, HH*NOPE, 8);
    // 6. v
    gemm_tf32<<<dim3(16, 32), 256>>>(CKV, WBr, V, BS, HH*VDIM, KVR, 128, 256, 128);
    gemm_t5<<<dim3(8, 32), 128, GEMM_SMEM>>>(CKVh, CKVl, WBvh, WBvl, V, HH*VDIM, 8);
    // 7. attention
    attn_kernel<<<dim3(SS/64, HH, BB), 256, ASMEM>>>(Q, KN, KPE, V, OH, OHh, OHl);
    // 8. out = OH @ wo^T
    gemm_tf32<<<dim3(16, 32), 256>>>(OH, WOr, out, BS, DIM, HH*VDIM, BIGGRP, 0, 0);
    gemm_t5<<<dim3(8, 32), 128, GEMM_SMEM>>>(OHh, OHl, WOh, WOl, out, DIM, 32);
}